// round 2
// baseline (speedup 1.0000x reference)
#include <cuda_runtime.h>
#include <math.h>

#define NB 8
#define NC 21
#define HW 4096
#define CF 768
#define NJ 42   // NC * 2

// ---------------- scratch (__device__ globals; no allocation allowed) ----------------
__device__ float g_featT[NB * HW * CF];   // [n][m][d]
__device__ float g_fnorm[NB * HW];        // ||feat[n,m]||
__device__ int   g_pcls[NB * HW];         // class of pixel if valid else -1
__device__ int   g_list[NB * NC * HW];    // valid pixel indices per (n,c), ascending
__device__ int   g_cnt[NB * NC];
__device__ float g_cent[NB * NJ * CF];    // [n][c*2+k][d]
__device__ float g_cnorm[NB * NJ];
__device__ float g_D[NB * NJ * HW];       // [n][j][m] = centers[j] . feat[m]
__device__ float g_Kmat[NB * NC * HW * 2];// [n][c][m][k]
__device__ float g_r[NB * NC * HW];

// ---------------- 1. transpose feature [n][cf][hw] -> featT [n][hw][cf] ----------------
__global__ void k_transpose(const float* __restrict__ feat) {
    __shared__ float tile[32][33];
    int n = blockIdx.z;
    int d0 = blockIdx.y * 32, m0 = blockIdx.x * 32;
    int tx = threadIdx.x;
    for (int i = threadIdx.y; i < 32; i += 8)
        tile[i][tx] = feat[(n * CF + d0 + i) * HW + m0 + tx];
    __syncthreads();
    for (int i = threadIdx.y; i < 32; i += 8)
        g_featT[(n * HW + m0 + i) * CF + d0 + tx] = tile[tx][i];
}

// ---------------- 2. per-pixel feature norms (warp per row) ----------------
__global__ void k_fnorm() {
    int w = (blockIdx.x * blockDim.x + threadIdx.x) >> 5;
    int lane = threadIdx.x & 31;
    if (w >= NB * HW) return;
    const float* row = g_featT + (size_t)w * CF;
    float s = 0.f;
    for (int d = lane; d < CF; d += 32) { float v = row[d]; s += v * v; }
    #pragma unroll
    for (int o = 16; o; o >>= 1) s += __shfl_xor_sync(0xffffffffu, s, o);
    if (!lane) g_fnorm[w] = sqrtf(s);
}

// ---------------- 3. argmax class per pixel, gated by label ----------------
__global__ void k_argmax(const float* __restrict__ cam, const float* __restrict__ label) {
    int idx = blockIdx.x * blockDim.x + threadIdx.x;
    if (idx >= NB * HW) return;
    int n = idx / HW, m = idx % HW;
    float best = cam[(n * NC) * HW + m];
    int bi = 0;
    for (int c = 1; c < NC; c++) {
        float v = cam[(n * NC + c) * HW + m];
        if (v > best) { best = v; bi = c; }   // first max on ties, like jnp.argmax
    }
    g_pcls[idx] = (label[n * NC + bi] > 0.f) ? bi : -1;
}

// ---------------- 4. ordered compaction: valid pixel lists per (n,c) (warp each) ----------------
__global__ void k_lists() {
    int w = (blockIdx.x * blockDim.x + threadIdx.x) >> 5;
    int lane = threadIdx.x & 31;
    if (w >= NB * NC) return;
    int n = w / NC, c = w % NC;
    int cnt = 0;
    int* lst = g_list + (size_t)w * HW;
    for (int base = 0; base < HW; base += 32) {
        int p = g_pcls[n * HW + base + lane];
        unsigned msk = __ballot_sync(0xffffffffu, p == c);
        if (p == c) lst[cnt + __popc(msk & ((1u << lane) - 1u))] = base + lane;
        cnt += __popc(msk);
    }
    if (!lane) g_cnt[w] = cnt;
}

// ---------------- 5. fused 10-iteration cosine k-means, block per (n,c) ----------------
__global__ void __launch_bounds__(128) k_kmeans() {
    __shared__ float cen[2][CF];
    __shared__ float part[4][2][CF];
    __shared__ int   pcntS[4][2];
    __shared__ float inv_s[2];
    __shared__ int   cnts[2];
    int bc = blockIdx.x;
    int n = bc / NC, c = bc % NC;
    int t = threadIdx.x, wid = t >> 5, lane = t & 31;
    int cnt = g_cnt[bc];
    float* gc = g_cent + ((size_t)n * NJ + c * 2) * CF;
    if (cnt < 2) {   // reference: centers forced to zero
        for (int i = t; i < 2 * CF; i += 128) gc[i] = 0.f;
        if (t < 2) g_cnorm[n * NJ + c * 2 + t] = 0.f;
        return;
    }
    const int* lst = g_list + (size_t)bc * HW;
    int i0 = lst[0], i1 = lst[1];   // first two valid pixels (label==1 -> mask scale 1)
    for (int d = t; d < CF; d += 128) {
        cen[0][d] = g_featT[((size_t)n * HW + i0) * CF + d];
        cen[1][d] = g_featT[((size_t)n * HW + i1) * CF + d];
    }
    __syncthreads();

    for (int iter = 0; iter < 10; iter++) {
        if (wid < 2) {   // center inverse norms (max with 1e-8)
            float s = 0.f;
            for (int d = lane; d < CF; d += 32) { float v = cen[wid][d]; s += v * v; }
            #pragma unroll
            for (int o = 16; o; o >>= 1) s += __shfl_xor_sync(0xffffffffu, s, o);
            if (!lane) inv_s[wid] = 1.f / fmaxf(sqrtf(s), 1e-8f);
        }
        for (int i = t; i < 4 * 2 * CF; i += 128) ((float*)part)[i] = 0.f;
        if (t < 8) ((int*)pcntS)[t] = 0;
        __syncthreads();
        float inv0 = inv_s[0], inv1 = inv_s[1];
        int myc0 = 0, myc1 = 0;
        for (int pi = wid; pi < cnt; pi += 4) {     // warp-per-pixel, fixed order
            int m = lst[pi];
            const float* fr = g_featT + ((size_t)n * HW + m) * CF;
            float v[24];
            float d0 = 0.f, d1 = 0.f;
            #pragma unroll
            for (int j2 = 0; j2 < 24; j2++) {
                float x = fr[lane + j2 * 32];
                v[j2] = x;
                d0 += x * cen[0][lane + j2 * 32];
                d1 += x * cen[1][lane + j2 * 32];
            }
            #pragma unroll
            for (int o = 16; o; o >>= 1) {
                d0 += __shfl_xor_sync(0xffffffffu, d0, o);
                d1 += __shfl_xor_sync(0xffffffffu, d1, o);
            }
            // feat_n common positive factor cancels in argmax; strict > == first-max ties
            int a = (d1 * inv1 > d0 * inv0) ? 1 : 0;
            #pragma unroll
            for (int j2 = 0; j2 < 24; j2++) part[wid][a][lane + j2 * 32] += v[j2];
            if (a) myc1++; else myc0++;
        }
        if (!lane) { pcntS[wid][0] = myc0; pcntS[wid][1] = myc1; }
        __syncthreads();
        if (t < 2) cnts[t] = pcntS[0][t] + pcntS[1][t] + pcntS[2][t] + pcntS[3][t];
        __syncthreads();
        float div0 = 1.f / fmaxf((float)cnts[0], 1.f);
        float div1 = 1.f / fmaxf((float)cnts[1], 1.f);
        for (int d = t; d < CF; d += 128) {
            cen[0][d] = (part[0][0][d] + part[1][0][d] + part[2][0][d] + part[3][0][d]) * div0;
            cen[1][d] = (part[0][1][d] + part[1][1][d] + part[2][1][d] + part[3][1][d]) * div1;
        }
        __syncthreads();
    }
    for (int d = t; d < CF; d += 128) { gc[d] = cen[0][d]; gc[CF + d] = cen[1][d]; }
    if (wid < 2) {
        float s = 0.f;
        for (int d = lane; d < CF; d += 32) { float v = cen[wid][d]; s += v * v; }
        #pragma unroll
        for (int o = 16; o; o >>= 1) s += __shfl_xor_sync(0xffffffffu, s, o);
        if (!lane) g_cnorm[n * NJ + c * 2 + wid] = sqrtf(s);
    }
}

// ---------------- 6. GEMM: D[n][j][m] = centers[n][j] . feat[n][m]  (42 x 4096 per n) ----------------
__global__ void __launch_bounds__(256) k_gemm() {
    __shared__ float fS[256][33];
    __shared__ float cS[NJ][33];
    int n = blockIdx.y, m0 = blockIdx.x * 256;
    int t = threadIdx.x;
    int p = t & 127, g = t >> 7;    // g uniform within each warp
    float acc0[21], acc1[21];
    #pragma unroll
    for (int j = 0; j < 21; j++) { acc0[j] = 0.f; acc1[j] = 0.f; }
    for (int d0 = 0; d0 < CF; d0 += 32) {
        __syncthreads();
        for (int idx = t; idx < 256 * 32; idx += 256) {
            int r = idx >> 5, dd = idx & 31;
            fS[r][dd] = g_featT[((size_t)n * HW + m0 + r) * CF + d0 + dd];
        }
        for (int idx = t; idx < NJ * 32; idx += 256) {
            int r = idx >> 5, dd = idx & 31;
            cS[r][dd] = g_cent[((size_t)n * NJ + r) * CF + d0 + dd];
        }
        __syncthreads();
        #pragma unroll 4
        for (int dd = 0; dd < 32; dd++) {
            float a0 = fS[p][dd], a1 = fS[p + 128][dd];
            #pragma unroll
            for (int j = 0; j < 21; j++) {
                float cc = cS[g * 21 + j][dd];
                acc0[j] += a0 * cc;
                acc1[j] += a1 * cc;
            }
        }
    }
    #pragma unroll
    for (int j = 0; j < 21; j++) {
        g_D[((size_t)n * NJ + g * 21 + j) * HW + m0 + p]       = acc0[j];
        g_D[((size_t)n * NJ + g * 21 + j) * HW + m0 + p + 128] = acc1[j];
    }
}

// ---------------- 7. cam * label (cosine mean over K, gated by cnt>=2) ----------------
__global__ void k_cam(const float* __restrict__ label, float* __restrict__ out) {
    int idx = blockIdx.x * blockDim.x + threadIdx.x;
    if (idx >= NB * NC * HW) return;
    int m = idx & (HW - 1);
    int nc = idx >> 12;
    int n = nc / NC, c = nc % NC;
    float outv = 0.f;
    if (g_cnt[nc] >= 2) {
        float fi = 1.f / fmaxf(g_fnorm[n * HW + m], 1e-8f);
        float d0 = g_D[((size_t)n * NJ + 2 * c) * HW + m];
        float d1 = g_D[((size_t)n * NJ + 2 * c + 1) * HW + m];
        float cos0 = d0 * fi / fmaxf(g_cnorm[n * NJ + 2 * c], 1e-8f);
        float cos1 = d1 * fi / fmaxf(g_cnorm[n * NJ + 2 * c + 1], 1e-8f);
        outv = 0.5f * (cos0 + cos1) * label[nc];
    }
    out[idx] = outv;
}

// ---------------- 8. per-(n,c) max normalize ----------------
__global__ void __launch_bounds__(256) k_normout(float* __restrict__ out) {
    __shared__ float red[256];
    int nc = blockIdx.x, t = threadIdx.x;
    float* o = out + (size_t)nc * HW;
    float mx = -INFINITY;
    for (int m = t; m < HW; m += 256) mx = fmaxf(mx, o[m]);
    red[t] = mx;
    __syncthreads();
    for (int s = 128; s; s >>= 1) { if (t < s) red[t] = fmaxf(red[t], red[t + s]); __syncthreads(); }
    float inv = 1.f / (red[0] + 1e-5f);
    for (int m = t; m < HW; m += 256) o[m] *= inv;
}

// ---------------- 9. Sinkhorn kernel matrix (faithful reshape quirk: j = k*21 + c) ----------------
__global__ void k_kmat() {
    int idx = blockIdx.x * blockDim.x + threadIdx.x;
    if (idx >= NB * NC * HW) return;
    int m = idx & (HW - 1);
    int nc = idx >> 12;
    int n = nc / NC, c = nc % NC;
    float nf = g_fnorm[n * HW + m] + 1e-5f;
    #pragma unroll
    for (int k = 0; k < 2; k++) {
        int j = k * NC + c;
        float sim = g_D[((size_t)n * NJ + j) * HW + m] / (nf * (g_cnorm[n * NJ + j] + 1e-5f));
        g_Kmat[(size_t)idx * 2 + k] = expf((sim - 1.f) * 10.f);
    }
}

// ---------------- 10. Sinkhorn with faithful early stop, block per n ----------------
__global__ void __launch_bounds__(1024) k_sinkhorn(float* __restrict__ Tout) {
    __shared__ float cv[NJ], cvn[NJ];
    __shared__ float red[1024];
    __shared__ float errS;
    int n = blockIdx.x, t = threadIdx.x, lane = t & 31, wid = t >> 5;
    const float u = 1.f / (float)HW, v = 0.5f;
    float* rg = g_r + (size_t)n * NC * HW;
    const float* Km = g_Kmat + (size_t)n * NC * HW * 2;
    if (t < NJ) cv[t] = 1.f;
    for (int i = t; i < NC * HW; i += 1024) rg[i] = 1.f;
    __syncthreads();

    for (int it = 0; it < 100; it++) {
        // r = u / (K @ c), accumulate |delta r|
        float errp = 0.f;
        for (int i = t; i < NC * HW; i += 1024) {
            int c = i >> 12;
            float den = Km[(size_t)i * 2] * cv[2 * c] + Km[(size_t)i * 2 + 1] * cv[2 * c + 1];
            float rn = u / den;
            errp += fabsf(rn - rg[i]);
            rg[i] = rn;
        }
        red[t] = errp;
        __syncthreads();
        for (int s = 512; s; s >>= 1) { if (t < s) red[t] += red[t + s]; __syncthreads(); }
        if (!t) errS = red[0] / (float)(NC * HW);
        // c = v / (K^T @ r): warp per (c,k) pair, deterministic lane-strided sums
        for (int pr = wid; pr < NJ; pr += 32) {
            int c = pr >> 1, k = pr & 1;
            const float* kp = Km + (size_t)(c * HW) * 2 + k;
            const float* rp = rg + c * HW;
            float s = 0.f;
            for (int m = lane; m < HW; m += 32) s += kp[(size_t)m * 2] * rp[m];
            #pragma unroll
            for (int o = 16; o; o >>= 1) s += __shfl_xor_sync(0xffffffffu, s, o);
            if (!lane) cvn[pr] = v / s;
        }
        __syncthreads();
        if (t < NJ) cv[t] = cvn[t];
        __syncthreads();
        if (errS < 0.01f) break;   // while (i<100 && err>=0.01)
    }
    // T[n][c][k][m] = r[c][m] * c[c][k] * K[c][m][k]
    for (int i = t; i < NC * HW * 2; i += 1024) {
        int c = i / (2 * HW);
        int k = (i / HW) & 1;
        int m = i & (HW - 1);
        Tout[(size_t)n * NC * 2 * HW + i] =
            rg[c * HW + m] * cv[2 * c + k] * Km[(size_t)(c * HW + m) * 2 + k];
    }
}

// ---------------- launcher ----------------
extern "C" void kernel_launch(void* const* d_in, const int* in_sizes, int n_in,
                              void* d_out, int out_size) {
    const float* norm_cam = (const float*)d_in[0];   // [8,21,64,64]
    const float* label    = (const float*)d_in[1];   // [8,21,1,1]
    const float* feature  = (const float*)d_in[2];   // [8,768,64,64]
    float* out  = (float*)d_out;                     // [8,21,64,64]
    float* Tout = out + NB * NC * HW;                // [8,21,2,64,64]

    k_transpose<<<dim3(HW / 32, CF / 32, NB), dim3(32, 8)>>>(feature);
    k_fnorm   <<<(NB * HW * 32 + 255) / 256, 256>>>();
    k_argmax  <<<(NB * HW + 255) / 256, 256>>>(norm_cam, label);
    k_lists   <<<(NB * NC * 32 + 255) / 256, 256>>>();
    k_kmeans  <<<NB * NC, 128>>>();
    k_gemm    <<<dim3(HW / 256, NB), 256>>>();
    k_cam     <<<(NB * NC * HW + 255) / 256, 256>>>(label, out);
    k_normout <<<NB * NC, 256>>>(out);
    k_kmat    <<<(NB * NC * HW + 255) / 256, 256>>>();
    k_sinkhorn<<<NB, 1024>>>(Tout);
}

// round 3
// speedup vs baseline: 1.4463x; 1.4463x over previous
#include <cuda_runtime.h>
#include <math.h>

#define NB 8
#define NC 21
#define HW 4096
#define CF 768
#define NJ 42   // NC * 2

// ---------------- scratch (__device__ globals; no allocation allowed) ----------------
__device__ float g_featT[NB * HW * CF];   // [n][m][d]
__device__ float g_fpart[24 * NB * HW];   // per-d-tile partial sumsq
__device__ float g_fnorm[NB * HW];        // ||feat[n,m]||
__device__ int   g_list[NB * NC * HW];    // valid pixel indices per (n,c), ascending
__device__ int   g_cnt[NB * NC];
__device__ float g_cent[NB * NJ * CF];    // [n][c*2+k][d]
__device__ float g_cnorm[NB * NJ];
__device__ float g_D[NB * NJ * HW];       // [n][j][m] = centers[j] . feat[m]
__device__ float g_Kmat[NB * NC * HW * 2];// [n][c][m][k]
__device__ float g_r[NB * NC * HW];

// ---------------- 1. transpose feature + per-column partial sumsq ----------------
__global__ void k_transpose(const float* __restrict__ feat) {
    __shared__ float tile[32][33];
    __shared__ float colp[8][33];
    int n = blockIdx.z;
    int d0 = blockIdx.y * 32, m0 = blockIdx.x * 32;
    int tx = threadIdx.x, ty = threadIdx.y;
    float acc = 0.f;
    for (int i = ty; i < 32; i += 8) {
        float v = feat[(n * CF + d0 + i) * HW + m0 + tx];
        tile[i][tx] = v;
        acc += v * v;
    }
    colp[ty][tx] = acc;
    __syncthreads();
    for (int i = ty; i < 32; i += 8)
        g_featT[((size_t)n * HW + m0 + i) * CF + d0 + tx] = tile[tx][i];
    if (ty == 0) {
        float s = 0.f;
        #pragma unroll
        for (int r = 0; r < 8; r++) s += colp[r][tx];
        g_fpart[blockIdx.y * (NB * HW) + n * HW + m0 + tx] = s;
    }
}

// ---------------- 2. finalize feature norms (deterministic 24-way sum) ----------------
__global__ void k_fnfin() {
    int idx = blockIdx.x * blockDim.x + threadIdx.x;
    if (idx >= NB * HW) return;
    float s = 0.f;
    #pragma unroll
    for (int k = 0; k < 24; k++) s += g_fpart[k * (NB * HW) + idx];
    g_fnorm[idx] = sqrtf(s);
}

// ---------------- 3. fused argmax + ordered compaction, block per n ----------------
__global__ void __launch_bounds__(1024) k_seed(const float* __restrict__ cam,
                                               const float* __restrict__ label) {
    __shared__ int spcls[HW];
    __shared__ float slab[NC];
    int n = blockIdx.x, t = threadIdx.x;
    if (t < NC) slab[t] = label[n * NC + t];
    __syncthreads();
    for (int m = t; m < HW; m += 1024) {
        const float* cp = cam + (size_t)n * NC * HW + m;
        float best = cp[0];
        int bi = 0;
        #pragma unroll
        for (int c = 1; c < NC; c++) {
            float v = cp[c * HW];
            if (v > best) { best = v; bi = c; }   // first max on ties
        }
        spcls[m] = (slab[bi] > 0.f) ? bi : -1;
    }
    __syncthreads();
    int w = t >> 5, lane = t & 31;
    if (w < NC) {
        int cnt = 0;
        int* lst = g_list + ((size_t)n * NC + w) * HW;
        for (int base = 0; base < HW; base += 32) {
            int p = spcls[base + lane];
            unsigned msk = __ballot_sync(0xffffffffu, p == w);
            if (p == w) lst[cnt + __popc(msk & ((1u << lane) - 1u))] = base + lane;
            cnt += __popc(msk);
        }
        if (!lane) g_cnt[n * NC + w] = cnt;
    }
}

// ---------------- 4. fused 10-iter cosine k-means: 8 warps, 2-px ILP, register accumulation --
__global__ void __launch_bounds__(256) k_kmeans() {
    extern __shared__ float buf[];
    float* cen  = buf;            // [2][CF]
    float* part = buf + 2 * CF;   // [8][2][CF]
    __shared__ int   pcnt[8][2];
    __shared__ float inv_s[2];
    __shared__ int   cnts[2];
    int bc = blockIdx.x;
    int n = bc / NC;
    int t = threadIdx.x, wid = t >> 5, lane = t & 31;
    int cnt = g_cnt[bc];
    float* gc = g_cent + (size_t)bc * 2 * CF;
    if (cnt < 2) {   // reference: centers forced to zero
        for (int i = t; i < 2 * CF; i += 256) gc[i] = 0.f;
        if (t < 2) g_cnorm[bc * 2 + t] = 0.f;
        return;
    }
    const int* lst = g_list + (size_t)bc * HW;
    int i0 = lst[0], i1 = lst[1];
    for (int d = t; d < CF; d += 256) {
        cen[d]      = g_featT[((size_t)n * HW + i0) * CF + d];
        cen[CF + d] = g_featT[((size_t)n * HW + i1) * CF + d];
    }
    __syncthreads();

    for (int iter = 0; iter < 10; iter++) {
        if (wid < 2) {   // center inverse norms
            float s = 0.f;
            for (int d = lane; d < CF; d += 32) { float v = cen[wid * CF + d]; s += v * v; }
            #pragma unroll
            for (int o = 16; o; o >>= 1) s += __shfl_xor_sync(0xffffffffu, s, o);
            if (!lane) inv_s[wid] = 1.f / fmaxf(sqrtf(s), 1e-8f);
        }
        __syncthreads();
        float inv0 = inv_s[0], inv1 = inv_s[1];
        float acc0[24], acc1[24];
        #pragma unroll
        for (int j = 0; j < 24; j++) { acc0[j] = 0.f; acc1[j] = 0.f; }
        int myc0 = 0, myc1 = 0;
        for (int pi = wid * 2; pi < cnt; pi += 16) {   // 2 pixels per warp step
            int m0 = lst[pi];
            int has = (pi + 1 < cnt);
            int m1 = has ? lst[pi + 1] : m0;
            const float* fa = g_featT + ((size_t)n * HW + m0) * CF + lane;
            const float* fb = g_featT + ((size_t)n * HW + m1) * CF + lane;
            float va[24], vb[24];
            float d0a = 0.f, d1a = 0.f, d0b = 0.f, d1b = 0.f;
            #pragma unroll
            for (int j = 0; j < 24; j++) {
                float c0 = cen[lane + j * 32];
                float c1 = cen[CF + lane + j * 32];
                float xa = fa[j * 32]; va[j] = xa; d0a += xa * c0; d1a += xa * c1;
                float xb = fb[j * 32]; vb[j] = xb; d0b += xb * c0; d1b += xb * c1;
            }
            #pragma unroll
            for (int o = 16; o; o >>= 1) {
                d0a += __shfl_xor_sync(0xffffffffu, d0a, o);
                d1a += __shfl_xor_sync(0xffffffffu, d1a, o);
                d0b += __shfl_xor_sync(0xffffffffu, d0b, o);
                d1b += __shfl_xor_sync(0xffffffffu, d1b, o);
            }
            int aa = (d1a * inv1 > d0a * inv0) ? 1 : 0;   // strict > == first-max ties
            int ab = (d1b * inv1 > d0b * inv0) ? 1 : 0;
            float w0a = aa ? 0.f : 1.f, w1a = aa ? 1.f : 0.f;
            float w0b = 0.f, w1b = 0.f;
            if (has) { w0b = ab ? 0.f : 1.f; w1b = ab ? 1.f : 0.f; }
            #pragma unroll
            for (int j = 0; j < 24; j++) {
                acc0[j] = fmaf(w0a, va[j], fmaf(w0b, vb[j], acc0[j]));
                acc1[j] = fmaf(w1a, va[j], fmaf(w1b, vb[j], acc1[j]));
            }
            myc0 += (1 - aa) + (has ? (1 - ab) : 0);
            myc1 += aa + (has ? ab : 0);
        }
        #pragma unroll
        for (int j = 0; j < 24; j++) {   // one smem dump per iteration
            part[(wid * 2 + 0) * CF + lane + j * 32] = acc0[j];
            part[(wid * 2 + 1) * CF + lane + j * 32] = acc1[j];
        }
        if (!lane) { pcnt[wid][0] = myc0; pcnt[wid][1] = myc1; }
        __syncthreads();
        if (t < 2) {
            int s = 0;
            #pragma unroll
            for (int w2 = 0; w2 < 8; w2++) s += pcnt[w2][t];
            cnts[t] = s;
        }
        __syncthreads();
        float div0 = 1.f / fmaxf((float)cnts[0], 1.f);
        float div1 = 1.f / fmaxf((float)cnts[1], 1.f);
        for (int d = t; d < CF; d += 256) {
            float s0 = 0.f, s1 = 0.f;
            #pragma unroll
            for (int w2 = 0; w2 < 8; w2++) {
                s0 += part[(w2 * 2) * CF + d];
                s1 += part[(w2 * 2 + 1) * CF + d];
            }
            cen[d] = s0 * div0;
            cen[CF + d] = s1 * div1;
        }
        __syncthreads();
    }
    for (int d = t; d < CF; d += 256) { gc[d] = cen[d]; gc[CF + d] = cen[CF + d]; }
    if (wid < 2) {
        float s = 0.f;
        for (int d = lane; d < CF; d += 32) { float v = cen[wid * CF + d]; s += v * v; }
        #pragma unroll
        for (int o = 16; o; o >>= 1) s += __shfl_xor_sync(0xffffffffu, s, o);
        if (!lane) g_cnorm[bc * 2 + wid] = sqrtf(s);
    }
}

// ---------------- 5. GEMM: D[n][j][m] = centers[n][j] . feat[n][m] ----------------
__global__ void __launch_bounds__(256) k_gemm() {
    __shared__ float fS[256][33];
    __shared__ float cS[NJ][33];
    int n = blockIdx.y, m0 = blockIdx.x * 256;
    int t = threadIdx.x;
    int p = t & 127, g = t >> 7;    // g uniform within each warp
    float acc0[21], acc1[21];
    #pragma unroll
    for (int j = 0; j < 21; j++) { acc0[j] = 0.f; acc1[j] = 0.f; }
    for (int d0 = 0; d0 < CF; d0 += 32) {
        __syncthreads();
        for (int idx = t; idx < 256 * 32; idx += 256) {
            int r = idx >> 5, dd = idx & 31;
            fS[r][dd] = g_featT[((size_t)n * HW + m0 + r) * CF + d0 + dd];
        }
        for (int idx = t; idx < NJ * 32; idx += 256) {
            int r = idx >> 5, dd = idx & 31;
            cS[r][dd] = g_cent[((size_t)n * NJ + r) * CF + d0 + dd];
        }
        __syncthreads();
        #pragma unroll 4
        for (int dd = 0; dd < 32; dd++) {
            float a0 = fS[p][dd], a1 = fS[p + 128][dd];
            #pragma unroll
            for (int j = 0; j < 21; j++) {
                float cc = cS[g * 21 + j][dd];
                acc0[j] += a0 * cc;
                acc1[j] += a1 * cc;
            }
        }
    }
    #pragma unroll
    for (int j = 0; j < 21; j++) {
        g_D[((size_t)n * NJ + g * 21 + j) * HW + m0 + p]       = acc0[j];
        g_D[((size_t)n * NJ + g * 21 + j) * HW + m0 + p + 128] = acc1[j];
    }
}

// ---------------- 6. fused cam + per-map max-normalize + Sinkhorn K matrix ----------------
__global__ void __launch_bounds__(256) k_camkmat(const float* __restrict__ label,
                                                 float* __restrict__ out) {
    __shared__ float scam[HW];
    __shared__ float red[256];
    int bc = blockIdx.x, n = bc / NC, c = bc % NC, t = threadIdx.x;
    int cnt = g_cnt[bc];
    float lab = label[bc];
    float inv_cn0 = 1.f / fmaxf(g_cnorm[n * NJ + 2 * c], 1e-8f);
    float inv_cn1 = 1.f / fmaxf(g_cnorm[n * NJ + 2 * c + 1], 1e-8f);
    float ik0 = 1.f / (g_cnorm[n * NJ + c] + 1e-5f);         // kmat quirk: j = k*21 + c
    float ik1 = 1.f / (g_cnorm[n * NJ + NC + c] + 1e-5f);
    const float* D0  = g_D + ((size_t)n * NJ + 2 * c) * HW;
    const float* D1  = D0 + HW;
    const float* Dk0 = g_D + ((size_t)n * NJ + c) * HW;
    const float* Dk1 = g_D + ((size_t)n * NJ + NC + c) * HW;
    float* Km = g_Kmat + (size_t)bc * HW * 2;
    float mx = -INFINITY;
    for (int m = t; m < HW; m += 256) {
        float fn = g_fnorm[n * HW + m];
        float camv = 0.f;
        if (cnt >= 2) {
            float fi = 1.f / fmaxf(fn, 1e-8f);
            camv = 0.5f * (D0[m] * inv_cn0 + D1[m] * inv_cn1) * fi * lab;
        }
        scam[m] = camv;
        mx = fmaxf(mx, camv);
        float fk = 1.f / (fn + 1e-5f);
        Km[m * 2 + 0] = expf((Dk0[m] * fk * ik0 - 1.f) * 10.f);
        Km[m * 2 + 1] = expf((Dk1[m] * fk * ik1 - 1.f) * 10.f);
    }
    red[t] = mx;
    __syncthreads();
    for (int s = 128; s; s >>= 1) { if (t < s) red[t] = fmaxf(red[t], red[t + s]); __syncthreads(); }
    float inv = 1.f / (red[0] + 1e-5f);
    for (int m = t; m < HW; m += 256) out[(size_t)bc * HW + m] = scam[m] * inv;
}

// ---------------- 7. Sinkhorn with faithful early stop, block per n ----------------
__global__ void __launch_bounds__(1024) k_sinkhorn(float* __restrict__ Tout) {
    __shared__ float cv[NJ], cvn[NJ];
    __shared__ float red[1024];
    __shared__ float errS;
    int n = blockIdx.x, t = threadIdx.x, lane = t & 31, wid = t >> 5;
    const float u = 1.f / (float)HW, v = 0.5f;
    float* rg = g_r + (size_t)n * NC * HW;
    const float* Km = g_Kmat + (size_t)n * NC * HW * 2;
    if (t < NJ) cv[t] = 1.f;
    for (int i = t; i < NC * HW; i += 1024) rg[i] = 1.f;
    __syncthreads();

    for (int it = 0; it < 100; it++) {
        float errp = 0.f;
        for (int i = t; i < NC * HW; i += 1024) {
            int c = i >> 12;
            float den = Km[(size_t)i * 2] * cv[2 * c] + Km[(size_t)i * 2 + 1] * cv[2 * c + 1];
            float rn = u / den;
            errp += fabsf(rn - rg[i]);
            rg[i] = rn;
        }
        red[t] = errp;
        __syncthreads();
        for (int s = 512; s; s >>= 1) { if (t < s) red[t] += red[t + s]; __syncthreads(); }
        if (!t) errS = red[0] / (float)(NC * HW);
        for (int pr = wid; pr < NJ; pr += 32) {
            int c = pr >> 1, k = pr & 1;
            const float* kp = Km + (size_t)(c * HW) * 2 + k;
            const float* rp = rg + c * HW;
            float s = 0.f;
            for (int m = lane; m < HW; m += 32) s += kp[(size_t)m * 2] * rp[m];
            #pragma unroll
            for (int o = 16; o; o >>= 1) s += __shfl_xor_sync(0xffffffffu, s, o);
            if (!lane) cvn[pr] = v / s;
        }
        __syncthreads();
        if (t < NJ) cv[t] = cvn[t];
        __syncthreads();
        if (errS < 0.01f) break;
    }
    for (int i = t; i < NC * HW * 2; i += 1024) {
        int c = i / (2 * HW);
        int k = (i / HW) & 1;
        int m = i & (HW - 1);
        Tout[(size_t)n * NC * 2 * HW + i] =
            rg[c * HW + m] * cv[2 * c + k] * Km[(size_t)(c * HW + m) * 2 + k];
    }
}

// ---------------- launcher ----------------
extern "C" void kernel_launch(void* const* d_in, const int* in_sizes, int n_in,
                              void* d_out, int out_size) {
    const float* norm_cam = (const float*)d_in[0];   // [8,21,64,64]
    const float* label    = (const float*)d_in[1];   // [8,21,1,1]
    const float* feature  = (const float*)d_in[2];   // [8,768,64,64]
    float* out  = (float*)d_out;                     // [8,21,64,64]
    float* Tout = out + NB * NC * HW;                // [8,21,2,64,64]

    const int KMEANS_SMEM = (2 * CF + 8 * 2 * CF) * sizeof(float);  // 55296 B
    cudaFuncSetAttribute(k_kmeans, cudaFuncAttributeMaxDynamicSharedMemorySize, KMEANS_SMEM);

    k_transpose<<<dim3(HW / 32, CF / 32, NB), dim3(32, 8)>>>(feature);
    k_fnfin   <<<(NB * HW + 255) / 256, 256>>>();
    k_seed    <<<NB, 1024>>>(norm_cam, label);
    k_kmeans  <<<NB * NC, 256, KMEANS_SMEM>>>();
    k_gemm    <<<dim3(HW / 256, NB), 256>>>();
    k_camkmat <<<NB * NC, 256>>>(label, out);
    k_sinkhorn<<<NB, 1024>>>(Tout);
}

// round 4
// speedup vs baseline: 1.5884x; 1.0983x over previous
#include <cuda_runtime.h>
#include <math.h>

#define NB 8
#define NC 21
#define HW 4096
#define CF 768
#define NJ 42   // NC * 2

// ---------------- scratch (__device__ globals; no allocation allowed) ----------------
__device__ float g_featT[NB * HW * CF];   // [n][m][d]
__device__ float g_fpart[24 * NB * HW];   // per-d-tile partial sumsq
__device__ float g_fnorm[NB * HW];        // ||feat[n,m]||
__device__ int   g_list[NB * NC * HW];    // valid pixel indices per (n,c), ascending
__device__ int   g_cnt[NB * NC];
__device__ float g_cent[NB * NJ * CF];    // [n][c*2+k][d]
__device__ float g_cnorm[NB * NJ];
__device__ float g_D[NB * NJ * HW];       // [n][j][m] = centers[j] . feat[m]
__device__ float g_Kmat[NB * NC * HW * 2];// [n][c][m][k]
__device__ float g_r[NB * NC * HW];

// ---------------- 1. transpose feature + per-column partial sumsq ----------------
__global__ void k_transpose(const float* __restrict__ feat) {
    __shared__ float tile[32][33];
    __shared__ float colp[8][33];
    int n = blockIdx.z;
    int d0 = blockIdx.y * 32, m0 = blockIdx.x * 32;
    int tx = threadIdx.x, ty = threadIdx.y;
    float acc = 0.f;
    for (int i = ty; i < 32; i += 8) {
        float v = feat[(n * CF + d0 + i) * HW + m0 + tx];
        tile[i][tx] = v;
        acc += v * v;
    }
    colp[ty][tx] = acc;
    __syncthreads();
    for (int i = ty; i < 32; i += 8)
        g_featT[((size_t)n * HW + m0 + i) * CF + d0 + tx] = tile[tx][i];
    if (ty == 0) {
        float s = 0.f;
        #pragma unroll
        for (int r = 0; r < 8; r++) s += colp[r][tx];
        g_fpart[blockIdx.y * (NB * HW) + n * HW + m0 + tx] = s;
    }
}

// ---------------- 2. finalize feature norms (deterministic 24-way sum) ----------------
__global__ void k_fnfin() {
    int idx = blockIdx.x * blockDim.x + threadIdx.x;
    if (idx >= NB * HW) return;
    float s = 0.f;
    #pragma unroll
    for (int k = 0; k < 24; k++) s += g_fpart[k * (NB * HW) + idx];
    g_fnorm[idx] = sqrtf(s);
}

// ---------------- 3. fused argmax + ordered compaction, block per n ----------------
__global__ void __launch_bounds__(1024) k_seed(const float* __restrict__ cam,
                                               const float* __restrict__ label) {
    __shared__ int spcls[HW];
    __shared__ float slab[NC];
    int n = blockIdx.x, t = threadIdx.x;
    if (t < NC) slab[t] = label[n * NC + t];
    __syncthreads();
    for (int m = t; m < HW; m += 1024) {
        const float* cp = cam + (size_t)n * NC * HW + m;
        float best = cp[0];
        int bi = 0;
        #pragma unroll
        for (int c = 1; c < NC; c++) {
            float v = cp[c * HW];
            if (v > best) { best = v; bi = c; }   // first max on ties
        }
        spcls[m] = (slab[bi] > 0.f) ? bi : -1;
    }
    __syncthreads();
    int w = t >> 5, lane = t & 31;
    if (w < NC) {
        int cnt = 0;
        int* lst = g_list + ((size_t)n * NC + w) * HW;
        for (int base = 0; base < HW; base += 32) {
            int p = spcls[base + lane];
            unsigned msk = __ballot_sync(0xffffffffu, p == w);
            if (p == w) lst[cnt + __popc(msk & ((1u << lane) - 1u))] = base + lane;
            cnt += __popc(msk);
        }
        if (!lane) g_cnt[n * NC + w] = cnt;
    }
}

// ---- 4. fused 10-iter cosine k-means: 8 warps, 1 px/warp-step, 2 blocks/SM ----
__global__ void __launch_bounds__(256, 2) k_kmeans() {
    extern __shared__ float buf[];
    float* cen  = buf;            // [2][CF]
    float* part = buf + 2 * CF;   // [8][2][CF]
    __shared__ int   pcnt[8][2];
    __shared__ float inv_s[2];
    __shared__ int   cnts[2];
    int bc = blockIdx.x;
    int n = bc / NC;
    int t = threadIdx.x, wid = t >> 5, lane = t & 31;
    int cnt = g_cnt[bc];
    float* gc = g_cent + (size_t)bc * 2 * CF;
    if (cnt < 2) {   // reference: centers forced to zero
        for (int i = t; i < 2 * CF; i += 256) gc[i] = 0.f;
        if (t < 2) g_cnorm[bc * 2 + t] = 0.f;
        return;
    }
    const int* lst = g_list + (size_t)bc * HW;
    int i0 = lst[0], i1 = lst[1];
    for (int d = t; d < CF; d += 256) {
        cen[d]      = g_featT[((size_t)n * HW + i0) * CF + d];
        cen[CF + d] = g_featT[((size_t)n * HW + i1) * CF + d];
    }
    __syncthreads();

    for (int iter = 0; iter < 10; iter++) {
        if (wid < 2) {   // center inverse norms
            float s = 0.f;
            for (int d = lane; d < CF; d += 32) { float v = cen[wid * CF + d]; s += v * v; }
            #pragma unroll
            for (int o = 16; o; o >>= 1) s += __shfl_xor_sync(0xffffffffu, s, o);
            if (!lane) inv_s[wid] = 1.f / fmaxf(sqrtf(s), 1e-8f);
        }
        __syncthreads();
        float inv0 = inv_s[0], inv1 = inv_s[1];
        float acc0[24], acc1[24];
        #pragma unroll
        for (int j = 0; j < 24; j++) { acc0[j] = 0.f; acc1[j] = 0.f; }
        int myc0 = 0, myc1 = 0;
        for (int pi = wid; pi < cnt; pi += 8) {    // 1 pixel per warp step
            int m = lst[pi];
            const float* fr = g_featT + ((size_t)n * HW + m) * CF + lane;
            float v[24];
            float d0 = 0.f, d1 = 0.f;
            #pragma unroll
            for (int j = 0; j < 24; j++) {
                float x = fr[j * 32];
                v[j] = x;
                d0 += x * cen[lane + j * 32];
                d1 += x * cen[CF + lane + j * 32];
            }
            #pragma unroll
            for (int o = 16; o; o >>= 1) {
                d0 += __shfl_xor_sync(0xffffffffu, d0, o);
                d1 += __shfl_xor_sync(0xffffffffu, d1, o);
            }
            // warp-uniform assignment; strict > == first-max on ties
            if (d1 * inv1 > d0 * inv0) {
                #pragma unroll
                for (int j = 0; j < 24; j++) acc1[j] += v[j];
                myc1++;
            } else {
                #pragma unroll
                for (int j = 0; j < 24; j++) acc0[j] += v[j];
                myc0++;
            }
        }
        #pragma unroll
        for (int j = 0; j < 24; j++) {   // one smem dump per iteration
            part[(wid * 2 + 0) * CF + lane + j * 32] = acc0[j];
            part[(wid * 2 + 1) * CF + lane + j * 32] = acc1[j];
        }
        if (!lane) { pcnt[wid][0] = myc0; pcnt[wid][1] = myc1; }
        __syncthreads();
        if (t < 2) {
            int s = 0;
            #pragma unroll
            for (int w2 = 0; w2 < 8; w2++) s += pcnt[w2][t];
            cnts[t] = s;
        }
        __syncthreads();
        float div0 = 1.f / fmaxf((float)cnts[0], 1.f);
        float div1 = 1.f / fmaxf((float)cnts[1], 1.f);
        for (int d = t; d < CF; d += 256) {
            float s0 = 0.f, s1 = 0.f;
            #pragma unroll
            for (int w2 = 0; w2 < 8; w2++) {
                s0 += part[(w2 * 2) * CF + d];
                s1 += part[(w2 * 2 + 1) * CF + d];
            }
            cen[d] = s0 * div0;
            cen[CF + d] = s1 * div1;
        }
        __syncthreads();
    }
    for (int d = t; d < CF; d += 256) { gc[d] = cen[d]; gc[CF + d] = cen[CF + d]; }
    if (wid < 2) {
        float s = 0.f;
        for (int d = lane; d < CF; d += 32) { float v = cen[wid * CF + d]; s += v * v; }
        #pragma unroll
        for (int o = 16; o; o >>= 1) s += __shfl_xor_sync(0xffffffffu, s, o);
        if (!lane) g_cnorm[bc * 2 + wid] = sqrtf(s);
    }
}

// ---- 5. GEMM: D[n][j][m] = centers[n][j].feat[n][m]; 4m x 21j register tile ----
#define GKT 96
#define GST 97   // padded row stride (conflict-free: bank = (row + dd) & 31)
__global__ void __launch_bounds__(128) k_gemm() {
    extern __shared__ float sm[];
    float* fS = sm;               // [256][GST]
    float* cS = sm + 256 * GST;   // [NJ][GST]
    int n = blockIdx.y, m0 = blockIdx.x * 256;
    int t = threadIdx.x;
    int p = t & 63;               // m lane (4 rows strided by 64)
    int g = t >> 6;               // j-group 0/1 (uniform per warp)
    float acc[4][21];
    #pragma unroll
    for (int i = 0; i < 4; i++)
        #pragma unroll
        for (int j = 0; j < 21; j++) acc[i][j] = 0.f;

    for (int k0 = 0; k0 < CF; k0 += GKT) {
        __syncthreads();
        // load feature tile: 256 rows x 96 cols as float4
        for (int fi = t; fi < 256 * 24; fi += 128) {
            int r = fi / 24, c4 = fi % 24;
            float4 v = *(const float4*)&g_featT[((size_t)n * HW + m0 + r) * CF + k0 + c4 * 4];
            float* dst = fS + r * GST + c4 * 4;
            dst[0] = v.x; dst[1] = v.y; dst[2] = v.z; dst[3] = v.w;
        }
        // load center tile: 42 rows x 96 cols
        for (int fi = t; fi < NJ * 24; fi += 128) {
            int r = fi / 24, c4 = fi % 24;
            float4 v = *(const float4*)&g_cent[((size_t)n * NJ + r) * CF + k0 + c4 * 4];
            float* dst = cS + r * GST + c4 * 4;
            dst[0] = v.x; dst[1] = v.y; dst[2] = v.z; dst[3] = v.w;
        }
        __syncthreads();
        #pragma unroll 2
        for (int dd = 0; dd < GKT; dd++) {
            float a0 = fS[p * GST + dd];
            float a1 = fS[(p + 64) * GST + dd];
            float a2 = fS[(p + 128) * GST + dd];
            float a3 = fS[(p + 192) * GST + dd];
            #pragma unroll
            for (int j = 0; j < 21; j++) {
                float cc = cS[(g * 21 + j) * GST + dd];   // broadcast LDS
                acc[0][j] += a0 * cc;
                acc[1][j] += a1 * cc;
                acc[2][j] += a2 * cc;
                acc[3][j] += a3 * cc;
            }
        }
    }
    #pragma unroll
    for (int j = 0; j < 21; j++) {
        float* dp = g_D + ((size_t)n * NJ + g * 21 + j) * HW + m0 + p;
        dp[0]   = acc[0][j];
        dp[64]  = acc[1][j];
        dp[128] = acc[2][j];
        dp[192] = acc[3][j];
    }
}

// ---------------- 6. fused cam + per-map max-normalize + Sinkhorn K matrix ----------------
__global__ void __launch_bounds__(256) k_camkmat(const float* __restrict__ label,
                                                 float* __restrict__ out) {
    __shared__ float scam[HW];
    __shared__ float red[256];
    int bc = blockIdx.x, n = bc / NC, c = bc % NC, t = threadIdx.x;
    int cnt = g_cnt[bc];
    float lab = label[bc];
    float inv_cn0 = 1.f / fmaxf(g_cnorm[n * NJ + 2 * c], 1e-8f);
    float inv_cn1 = 1.f / fmaxf(g_cnorm[n * NJ + 2 * c + 1], 1e-8f);
    float ik0 = 1.f / (g_cnorm[n * NJ + c] + 1e-5f);         // kmat quirk: j = k*21 + c
    float ik1 = 1.f / (g_cnorm[n * NJ + NC + c] + 1e-5f);
    const float* D0  = g_D + ((size_t)n * NJ + 2 * c) * HW;
    const float* D1  = D0 + HW;
    const float* Dk0 = g_D + ((size_t)n * NJ + c) * HW;
    const float* Dk1 = g_D + ((size_t)n * NJ + NC + c) * HW;
    float* Km = g_Kmat + (size_t)bc * HW * 2;
    float mx = -INFINITY;
    for (int m = t; m < HW; m += 256) {
        float fn = g_fnorm[n * HW + m];
        float camv = 0.f;
        if (cnt >= 2) {
            float fi = 1.f / fmaxf(fn, 1e-8f);
            camv = 0.5f * (D0[m] * inv_cn0 + D1[m] * inv_cn1) * fi * lab;
        }
        scam[m] = camv;
        mx = fmaxf(mx, camv);
        float fk = 1.f / (fn + 1e-5f);
        Km[m * 2 + 0] = expf((Dk0[m] * fk * ik0 - 1.f) * 10.f);
        Km[m * 2 + 1] = expf((Dk1[m] * fk * ik1 - 1.f) * 10.f);
    }
    red[t] = mx;
    __syncthreads();
    for (int s = 128; s; s >>= 1) { if (t < s) red[t] = fmaxf(red[t], red[t + s]); __syncthreads(); }
    float inv = 1.f / (red[0] + 1e-5f);
    for (int m = t; m < HW; m += 256) out[(size_t)bc * HW + m] = scam[m] * inv;
}

// ---------------- 7. Sinkhorn with faithful early stop, block per n ----------------
__global__ void __launch_bounds__(1024) k_sinkhorn(float* __restrict__ Tout) {
    __shared__ float cv[NJ], cvn[NJ];
    __shared__ float red[1024];
    __shared__ float errS;
    int n = blockIdx.x, t = threadIdx.x, lane = t & 31, wid = t >> 5;
    const float u = 1.f / (float)HW, v = 0.5f;
    float* rg = g_r + (size_t)n * NC * HW;
    const float* Km = g_Kmat + (size_t)n * NC * HW * 2;
    if (t < NJ) cv[t] = 1.f;
    for (int i = t; i < NC * HW; i += 1024) rg[i] = 1.f;
    __syncthreads();

    for (int it = 0; it < 100; it++) {
        float errp = 0.f;
        for (int i = t; i < NC * HW; i += 1024) {
            int c = i >> 12;
            float den = Km[(size_t)i * 2] * cv[2 * c] + Km[(size_t)i * 2 + 1] * cv[2 * c + 1];
            float rn = u / den;
            errp += fabsf(rn - rg[i]);
            rg[i] = rn;
        }
        red[t] = errp;
        __syncthreads();
        for (int s = 512; s; s >>= 1) { if (t < s) red[t] += red[t + s]; __syncthreads(); }
        if (!t) errS = red[0] / (float)(NC * HW);
        for (int pr = wid; pr < NJ; pr += 32) {
            int c = pr >> 1, k = pr & 1;
            const float* kp = Km + (size_t)(c * HW) * 2 + k;
            const float* rp = rg + c * HW;
            float s = 0.f;
            for (int m = lane; m < HW; m += 32) s += kp[(size_t)m * 2] * rp[m];
            #pragma unroll
            for (int o = 16; o; o >>= 1) s += __shfl_xor_sync(0xffffffffu, s, o);
            if (!lane) cvn[pr] = v / s;
        }
        __syncthreads();
        if (t < NJ) cv[t] = cvn[t];
        __syncthreads();
        if (errS < 0.01f) break;
    }
    for (int i = t; i < NC * HW * 2; i += 1024) {
        int c = i / (2 * HW);
        int k = (i / HW) & 1;
        int m = i & (HW - 1);
        Tout[(size_t)n * NC * 2 * HW + i] =
            rg[c * HW + m] * cv[2 * c + k] * Km[(size_t)(c * HW + m) * 2 + k];
    }
}

// ---------------- launcher ----------------
extern "C" void kernel_launch(void* const* d_in, const int* in_sizes, int n_in,
                              void* d_out, int out_size) {
    const float* norm_cam = (const float*)d_in[0];   // [8,21,64,64]
    const float* label    = (const float*)d_in[1];   // [8,21,1,1]
    const float* feature  = (const float*)d_in[2];   // [8,768,64,64]
    float* out  = (float*)d_out;                     // [8,21,64,64]
    float* Tout = out + NB * NC * HW;                // [8,21,2,64,64]

    const int KMEANS_SMEM = (2 * CF + 8 * 2 * CF) * sizeof(float);       // 55296 B
    const int GEMM_SMEM   = (256 * GST + NJ * GST) * sizeof(float);      // ~115.6 KB
    cudaFuncSetAttribute(k_kmeans, cudaFuncAttributeMaxDynamicSharedMemorySize, KMEANS_SMEM);
    cudaFuncSetAttribute(k_gemm,   cudaFuncAttributeMaxDynamicSharedMemorySize, GEMM_SMEM);

    k_transpose<<<dim3(HW / 32, CF / 32, NB), dim3(32, 8)>>>(feature);
    k_fnfin   <<<(NB * HW + 255) / 256, 256>>>();
    k_seed    <<<NB, 1024>>>(norm_cam, label);
    k_kmeans  <<<NB * NC, 256, KMEANS_SMEM>>>();
    k_gemm    <<<dim3(HW / 256, NB), 128, GEMM_SMEM>>>();
    k_camkmat <<<NB * NC, 256>>>(label, out);
    k_sinkhorn<<<NB, 1024>>>(Tout);
}

// round 5
// speedup vs baseline: 1.6631x; 1.0470x over previous
#include <cuda_runtime.h>
#include <math.h>

#define NB 8
#define NC 21
#define HW 4096
#define CF 768
#define NJ 42   // NC * 2

// ---------------- scratch (__device__ globals; no allocation allowed) ----------------
__device__ float g_featT[NB * HW * CF];   // [n][m][d]
__device__ float g_fpart[24 * NB * HW];   // per-d-tile partial sumsq
__device__ float g_fnorm[NB * HW];        // ||feat[n,m]||
__device__ int   g_list[NB * NC * HW];    // valid pixel indices per (n,c), ascending
__device__ int   g_cnt[NB * NC];
__device__ float g_cent[NB * NJ * CF];    // [n][c*2+k][d]
__device__ float g_cnorm[NB * NJ];
__device__ float g_D[NB * NJ * HW];       // [n][j][m] = centers[j] . feat[m]
__device__ float g_Kmat[NB * NC * HW * 2];// [n][c][m][k]
__device__ float g_r[NB * NC * HW];

// packed f32x2 FMA (FFMA2): d = a*b + d, lane-wise on 2 packed floats
#define FMA_F32X2(d, a, b) \
    asm("fma.rn.f32x2 %0, %1, %2, %0;" : "+l"(d) : "l"(a), "l"(b))

// ---------------- 1. transpose feature + per-column partial sumsq ----------------
__global__ void k_transpose(const float* __restrict__ feat) {
    __shared__ float tile[32][33];
    __shared__ float colp[8][33];
    int n = blockIdx.z;
    int d0 = blockIdx.y * 32, m0 = blockIdx.x * 32;
    int tx = threadIdx.x, ty = threadIdx.y;
    float acc = 0.f;
    for (int i = ty; i < 32; i += 8) {
        float v = feat[(n * CF + d0 + i) * HW + m0 + tx];
        tile[i][tx] = v;
        acc += v * v;
    }
    colp[ty][tx] = acc;
    __syncthreads();
    for (int i = ty; i < 32; i += 8)
        g_featT[((size_t)n * HW + m0 + i) * CF + d0 + tx] = tile[tx][i];
    if (ty == 0) {
        float s = 0.f;
        #pragma unroll
        for (int r = 0; r < 8; r++) s += colp[r][tx];
        g_fpart[blockIdx.y * (NB * HW) + n * HW + m0 + tx] = s;
    }
}

// ---------------- 2. finalize feature norms (deterministic 24-way sum) ----------------
__global__ void k_fnfin() {
    int idx = blockIdx.x * blockDim.x + threadIdx.x;
    if (idx >= NB * HW) return;
    float s = 0.f;
    #pragma unroll
    for (int k = 0; k < 24; k++) s += g_fpart[k * (NB * HW) + idx];
    g_fnorm[idx] = sqrtf(s);
}

// ---------------- 3. fused argmax + ordered compaction, block per n ----------------
__global__ void __launch_bounds__(1024) k_seed(const float* __restrict__ cam,
                                               const float* __restrict__ label) {
    __shared__ int spcls[HW];
    __shared__ float slab[NC];
    int n = blockIdx.x, t = threadIdx.x;
    if (t < NC) slab[t] = label[n * NC + t];
    __syncthreads();
    for (int m = t; m < HW; m += 1024) {
        const float* cp = cam + (size_t)n * NC * HW + m;
        float best = cp[0];
        int bi = 0;
        #pragma unroll
        for (int c = 1; c < NC; c++) {
            float v = cp[c * HW];
            if (v > best) { best = v; bi = c; }   // first max on ties
        }
        spcls[m] = (slab[bi] > 0.f) ? bi : -1;
    }
    __syncthreads();
    int w = t >> 5, lane = t & 31;
    if (w < NC) {
        int cnt = 0;
        int* lst = g_list + ((size_t)n * NC + w) * HW;
        for (int base = 0; base < HW; base += 32) {
            int p = spcls[base + lane];
            unsigned msk = __ballot_sync(0xffffffffu, p == w);
            if (p == w) lst[cnt + __popc(msk & ((1u << lane) - 1u))] = base + lane;
            cnt += __popc(msk);
        }
        if (!lane) g_cnt[n * NC + w] = cnt;
    }
}

// ---- 4. fused 10-iter cosine k-means: 5 warps, 2-px ILP, 2 blocks/SM, 1 wave ----
#define KW 5   // warps per kmeans block
__global__ void __launch_bounds__(32 * KW, 2) k_kmeans() {
    extern __shared__ float buf[];
    float* cen  = buf;            // [2][CF]
    float* part = buf + 2 * CF;   // [KW][2][CF]
    __shared__ int   pcnt[KW][2];
    __shared__ float inv_s[2];
    __shared__ int   cnts[2];
    int bc = blockIdx.x;
    int n = bc / NC;
    int t = threadIdx.x, wid = t >> 5, lane = t & 31;
    int cnt = g_cnt[bc];
    float* gc = g_cent + (size_t)bc * 2 * CF;
    if (cnt < 2) {   // reference: centers forced to zero
        for (int i = t; i < 2 * CF; i += 32 * KW) gc[i] = 0.f;
        if (t < 2) g_cnorm[bc * 2 + t] = 0.f;
        return;
    }
    const int* lst = g_list + (size_t)bc * HW;
    int i0 = lst[0], i1 = lst[1];
    for (int d = t; d < CF; d += 32 * KW) {
        cen[d]      = g_featT[((size_t)n * HW + i0) * CF + d];
        cen[CF + d] = g_featT[((size_t)n * HW + i1) * CF + d];
    }
    __syncthreads();

    for (int iter = 0; iter < 10; iter++) {
        if (wid < 2) {   // center inverse norms
            float s = 0.f;
            for (int d = lane; d < CF; d += 32) { float v = cen[wid * CF + d]; s += v * v; }
            #pragma unroll
            for (int o = 16; o; o >>= 1) s += __shfl_xor_sync(0xffffffffu, s, o);
            if (!lane) inv_s[wid] = 1.f / fmaxf(sqrtf(s), 1e-8f);
        }
        __syncthreads();
        float inv0 = inv_s[0], inv1 = inv_s[1];
        float acc0[24], acc1[24];
        #pragma unroll
        for (int j = 0; j < 24; j++) { acc0[j] = 0.f; acc1[j] = 0.f; }
        int myc0 = 0, myc1 = 0;
        for (int pi = wid * 2; pi < cnt; pi += 2 * KW) {   // 2 pixels per warp step
            int m0 = lst[pi];
            int has = (pi + 1 < cnt);
            int m1 = has ? lst[pi + 1] : m0;
            const float* fa = g_featT + ((size_t)n * HW + m0) * CF + lane;
            const float* fb = g_featT + ((size_t)n * HW + m1) * CF + lane;
            float va[24], vb[24];
            float d0a = 0.f, d1a = 0.f, d0b = 0.f, d1b = 0.f;
            #pragma unroll
            for (int j = 0; j < 24; j++) {
                float c0 = cen[lane + j * 32];
                float c1 = cen[CF + lane + j * 32];
                float xa = fa[j * 32]; va[j] = xa; d0a += xa * c0; d1a += xa * c1;
                float xb = fb[j * 32]; vb[j] = xb; d0b += xb * c0; d1b += xb * c1;
            }
            #pragma unroll
            for (int o = 16; o; o >>= 1) {
                d0a += __shfl_xor_sync(0xffffffffu, d0a, o);
                d1a += __shfl_xor_sync(0xffffffffu, d1a, o);
                d0b += __shfl_xor_sync(0xffffffffu, d0b, o);
                d1b += __shfl_xor_sync(0xffffffffu, d1b, o);
            }
            int aa = (d1a * inv1 > d0a * inv0) ? 1 : 0;   // strict > == first-max ties
            int ab = (d1b * inv1 > d0b * inv0) ? 1 : 0;
            float w0a = aa ? 0.f : 1.f, w1a = aa ? 1.f : 0.f;
            float w0b = 0.f, w1b = 0.f;
            if (has) { w0b = ab ? 0.f : 1.f; w1b = ab ? 1.f : 0.f; }
            #pragma unroll
            for (int j = 0; j < 24; j++) {
                acc0[j] = fmaf(w0a, va[j], fmaf(w0b, vb[j], acc0[j]));
                acc1[j] = fmaf(w1a, va[j], fmaf(w1b, vb[j], acc1[j]));
            }
            myc0 += (1 - aa) + (has ? (1 - ab) : 0);
            myc1 += aa + (has ? ab : 0);
        }
        #pragma unroll
        for (int j = 0; j < 24; j++) {   // one smem dump per iteration
            part[(wid * 2 + 0) * CF + lane + j * 32] = acc0[j];
            part[(wid * 2 + 1) * CF + lane + j * 32] = acc1[j];
        }
        if (!lane) { pcnt[wid][0] = myc0; pcnt[wid][1] = myc1; }
        __syncthreads();
        if (t < 2) {
            int s = 0;
            #pragma unroll
            for (int w2 = 0; w2 < KW; w2++) s += pcnt[w2][t];
            cnts[t] = s;
        }
        __syncthreads();
        float div0 = 1.f / fmaxf((float)cnts[0], 1.f);
        float div1 = 1.f / fmaxf((float)cnts[1], 1.f);
        for (int d = t; d < CF; d += 32 * KW) {
            float s0 = 0.f, s1 = 0.f;
            #pragma unroll
            for (int w2 = 0; w2 < KW; w2++) {
                s0 += part[(w2 * 2) * CF + d];
                s1 += part[(w2 * 2 + 1) * CF + d];
            }
            cen[d] = s0 * div0;
            cen[CF + d] = s1 * div1;
        }
        __syncthreads();
    }
    for (int d = t; d < CF; d += 32 * KW) { gc[d] = cen[d]; gc[CF + d] = cen[CF + d]; }
    if (wid < 2) {
        float s = 0.f;
        for (int d = lane; d < CF; d += 32) { float v = cen[wid * CF + d]; s += v * v; }
        #pragma unroll
        for (int o = 16; o; o >>= 1) s += __shfl_xor_sync(0xffffffffu, s, o);
        if (!lane) g_cnorm[bc * 2 + wid] = sqrtf(s);
    }
}

// ---- 5. GEMM via packed f32x2 FMA: D[n][j][m] = centers[n][j].feat[n][m] ----
// Reads ORIGINAL feature layout [n][d][hw] (dd-major smem tile, no transpose dep).
// Each thread: 4 m-columns (2 f32x2 pairs) x 21 j. Centers staged as (c,c) pairs
// so one 16B broadcast LDS serves 2 dd steps.
#define GT 48   // k-tile
__global__ void __launch_bounds__(128) k_gemm(const float* __restrict__ feat) {
    extern __shared__ float sm[];
    float* fS = sm;                                            // [GT][256]
    unsigned long long* cS2 = (unsigned long long*)(sm + GT * 256);  // [NJ][GT]
    int n = blockIdx.y, m0 = blockIdx.x * 256;
    int t = threadIdx.x;
    int p = t & 63, g = t >> 6;    // g = j-group (warp-uniform)
    unsigned long long acc[2][21];
    #pragma unroll
    for (int i = 0; i < 2; i++)
        #pragma unroll
        for (int j = 0; j < 21; j++) acc[i][j] = 0ull;

    for (int k0 = 0; k0 < CF; k0 += GT) {
        __syncthreads();
        // feature tile: GT rows of 256 m, float4 coalesced
        for (int idx = t; idx < GT * 64; idx += 128) {
            int dd = idx >> 6, c4 = idx & 63;
            float4 v = *(const float4*)&feat[((size_t)(n * CF + k0 + dd)) * HW + m0 + c4 * 4];
            *(float4*)&fS[dd * 256 + c4 * 4] = v;
        }
        // center tile as duplicated (c,c) pairs
        for (int idx = t; idx < NJ * GT; idx += 128) {
            int j = idx / GT, dd = idx % GT;
            float v = g_cent[((size_t)n * NJ + j) * CF + k0 + dd];
            float2 d2 = make_float2(v, v);
            cS2[j * GT + dd] = *(unsigned long long*)&d2;
        }
        __syncthreads();
        #pragma unroll 4
        for (int dd = 0; dd < GT; dd += 2) {
            unsigned long long a00 = *(const unsigned long long*)&fS[dd * 256 + 2 * p];
            unsigned long long a01 = *(const unsigned long long*)&fS[dd * 256 + 128 + 2 * p];
            unsigned long long a10 = *(const unsigned long long*)&fS[(dd + 1) * 256 + 2 * p];
            unsigned long long a11 = *(const unsigned long long*)&fS[(dd + 1) * 256 + 128 + 2 * p];
            const ulonglong2* crow = (const ulonglong2*)&cS2[(g * 21) * GT + dd];
            #pragma unroll
            for (int j = 0; j < 21; j++) {
                ulonglong2 c2 = *(const ulonglong2*)&cS2[(g * 21 + j) * GT + dd];
                FMA_F32X2(acc[0][j], a00, c2.x);
                FMA_F32X2(acc[1][j], a01, c2.x);
                FMA_F32X2(acc[0][j], a10, c2.y);
                FMA_F32X2(acc[1][j], a11, c2.y);
            }
            (void)crow;
        }
    }
    #pragma unroll
    for (int j = 0; j < 21; j++) {
        float* dp = g_D + ((size_t)n * NJ + g * 21 + j) * HW + m0;
        *(float2*)&dp[2 * p]       = *(float2*)&acc[0][j];
        *(float2*)&dp[128 + 2 * p] = *(float2*)&acc[1][j];
    }
}

// ---------------- 6. fused cam + per-map max-normalize + Sinkhorn K matrix ----------------
__global__ void __launch_bounds__(256) k_camkmat(const float* __restrict__ label,
                                                 float* __restrict__ out) {
    __shared__ float scam[HW];
    __shared__ float red[256];
    int bc = blockIdx.x, n = bc / NC, c = bc % NC, t = threadIdx.x;
    int cnt = g_cnt[bc];
    float lab = label[bc];
    float inv_cn0 = 1.f / fmaxf(g_cnorm[n * NJ + 2 * c], 1e-8f);
    float inv_cn1 = 1.f / fmaxf(g_cnorm[n * NJ + 2 * c + 1], 1e-8f);
    float ik0 = 1.f / (g_cnorm[n * NJ + c] + 1e-5f);         // kmat quirk: j = k*21 + c
    float ik1 = 1.f / (g_cnorm[n * NJ + NC + c] + 1e-5f);
    const float* D0  = g_D + ((size_t)n * NJ + 2 * c) * HW;
    const float* D1  = D0 + HW;
    const float* Dk0 = g_D + ((size_t)n * NJ + c) * HW;
    const float* Dk1 = g_D + ((size_t)n * NJ + NC + c) * HW;
    float* Km = g_Kmat + (size_t)bc * HW * 2;
    float mx = -INFINITY;
    for (int m = t; m < HW; m += 256) {
        float fn = g_fnorm[n * HW + m];
        float camv = 0.f;
        if (cnt >= 2) {
            float fi = 1.f / fmaxf(fn, 1e-8f);
            camv = 0.5f * (D0[m] * inv_cn0 + D1[m] * inv_cn1) * fi * lab;
        }
        scam[m] = camv;
        mx = fmaxf(mx, camv);
        float fk = 1.f / (fn + 1e-5f);
        Km[m * 2 + 0] = expf((Dk0[m] * fk * ik0 - 1.f) * 10.f);
        Km[m * 2 + 1] = expf((Dk1[m] * fk * ik1 - 1.f) * 10.f);
    }
    red[t] = mx;
    __syncthreads();
    for (int s = 128; s; s >>= 1) { if (t < s) red[t] = fmaxf(red[t], red[t + s]); __syncthreads(); }
    float inv = 1.f / (red[0] + 1e-5f);
    for (int m = t; m < HW; m += 256) out[(size_t)bc * HW + m] = scam[m] * inv;
}

// ---------------- 7. Sinkhorn with faithful early stop, block per n ----------------
__global__ void __launch_bounds__(1024) k_sinkhorn(float* __restrict__ Tout) {
    __shared__ float cv[NJ], cvn[NJ];
    __shared__ float red[1024];
    __shared__ float errS;
    int n = blockIdx.x, t = threadIdx.x, lane = t & 31, wid = t >> 5;
    const float u = 1.f / (float)HW, v = 0.5f;
    float* rg = g_r + (size_t)n * NC * HW;
    const float* Km = g_Kmat + (size_t)n * NC * HW * 2;
    if (t < NJ) cv[t] = 1.f;
    for (int i = t; i < NC * HW; i += 1024) rg[i] = 1.f;
    __syncthreads();

    for (int it = 0; it < 100; it++) {
        float errp = 0.f;
        for (int i = t; i < NC * HW; i += 1024) {
            int c = i >> 12;
            float den = Km[(size_t)i * 2] * cv[2 * c] + Km[(size_t)i * 2 + 1] * cv[2 * c + 1];
            float rn = u / den;
            errp += fabsf(rn - rg[i]);
            rg[i] = rn;
        }
        red[t] = errp;
        __syncthreads();
        for (int s = 512; s; s >>= 1) { if (t < s) red[t] += red[t + s]; __syncthreads(); }
        if (!t) errS = red[0] / (float)(NC * HW);
        for (int pr = wid; pr < NJ; pr += 32) {
            int c = pr >> 1, k = pr & 1;
            const float* kp = Km + (size_t)(c * HW) * 2 + k;
            const float* rp = rg + c * HW;
            float s = 0.f;
            for (int m = lane; m < HW; m += 32) s += kp[(size_t)m * 2] * rp[m];
            #pragma unroll
            for (int o = 16; o; o >>= 1) s += __shfl_xor_sync(0xffffffffu, s, o);
            if (!lane) cvn[pr] = v / s;
        }
        __syncthreads();
        if (t < NJ) cv[t] = cvn[t];
        __syncthreads();
        if (errS < 0.01f) break;
    }
    for (int i = t; i < NC * HW * 2; i += 1024) {
        int c = i / (2 * HW);
        int k = (i / HW) & 1;
        int m = i & (HW - 1);
        Tout[(size_t)n * NC * 2 * HW + i] =
            rg[c * HW + m] * cv[2 * c + k] * Km[(size_t)(c * HW + m) * 2 + k];
    }
}

// ---------------- launcher ----------------
extern "C" void kernel_launch(void* const* d_in, const int* in_sizes, int n_in,
                              void* d_out, int out_size) {
    const float* norm_cam = (const float*)d_in[0];   // [8,21,64,64]
    const float* label    = (const float*)d_in[1];   // [8,21,1,1]
    const float* feature  = (const float*)d_in[2];   // [8,768,64,64]
    float* out  = (float*)d_out;                     // [8,21,64,64]
    float* Tout = out + NB * NC * HW;                // [8,21,2,64,64]

    const int KMEANS_SMEM = (2 * CF + KW * 2 * CF) * sizeof(float);      // 36864 B
    const int GEMM_SMEM   = GT * 256 * 4 + NJ * GT * 8;                  // 65280 B
    cudaFuncSetAttribute(k_kmeans, cudaFuncAttributeMaxDynamicSharedMemorySize, KMEANS_SMEM);
    cudaFuncSetAttribute(k_gemm,   cudaFuncAttributeMaxDynamicSharedMemorySize, GEMM_SMEM);

    k_transpose<<<dim3(HW / 32, CF / 32, NB), dim3(32, 8)>>>(feature);
    k_fnfin   <<<(NB * HW + 255) / 256, 256>>>();
    k_seed    <<<NB, 1024>>>(norm_cam, label);
    k_kmeans  <<<NB * NC, 32 * KW, KMEANS_SMEM>>>();
    k_gemm    <<<dim3(HW / 256, NB), 128, GEMM_SMEM>>>(feature);
    k_camkmat <<<NB * NC, 256>>>(label, out);
    k_sinkhorn<<<NB, 1024>>>(Tout);
}

// round 6
// speedup vs baseline: 1.9325x; 1.1620x over previous
#include <cuda_runtime.h>
#include <math.h>

#define NB 8
#define NC 21
#define HW 4096
#define CF 768
#define NJ 42   // NC * 2

// ---------------- scratch (__device__ globals; no allocation allowed) ----------------
__device__ float g_featT[NB * HW * CF];   // [n][m][d]
__device__ float g_fpart[24 * NB * HW];   // per-d-tile partial sumsq
__device__ float g_fnorm[NB * HW];        // ||feat[n,m]||
__device__ int   g_list[NB * NC * HW];    // valid pixel indices per (n,c), ascending
__device__ int   g_cnt[NB * NC];
__device__ float g_cent[NB * NJ * CF];    // [n][c*2+k][d]
__device__ float g_cnorm[NB * NJ];
__device__ float g_D[NB * NJ * HW];       // [n][j][m] = centers[j] . feat[m]
__device__ float g_Kmat[NB * NC * HW * 2];// [n][c][m][k]
__device__ float g_r[NB * NC * HW];

// packed f32x2 FMA (FFMA2): d = a*b + d, lane-wise on 2 packed floats
#define FMA_F32X2(d, a, b) \
    asm("fma.rn.f32x2 %0, %1, %2, %0;" : "+l"(d) : "l"(a), "l"(b))

// ---------------- 1. transpose feature + per-column partial sumsq ----------------
__global__ void k_transpose(const float* __restrict__ feat) {
    __shared__ float tile[32][33];
    __shared__ float colp[8][33];
    int n = blockIdx.z;
    int d0 = blockIdx.y * 32, m0 = blockIdx.x * 32;
    int tx = threadIdx.x, ty = threadIdx.y;
    float acc = 0.f;
    for (int i = ty; i < 32; i += 8) {
        float v = feat[(n * CF + d0 + i) * HW + m0 + tx];
        tile[i][tx] = v;
        acc += v * v;
    }
    colp[ty][tx] = acc;
    __syncthreads();
    for (int i = ty; i < 32; i += 8)
        g_featT[((size_t)n * HW + m0 + i) * CF + d0 + tx] = tile[tx][i];
    if (ty == 0) {
        float s = 0.f;
        #pragma unroll
        for (int r = 0; r < 8; r++) s += colp[r][tx];
        g_fpart[blockIdx.y * (NB * HW) + n * HW + m0 + tx] = s;
    }
}

// ---------------- 2. finalize feature norms (deterministic 24-way sum) ----------------
__global__ void k_fnfin() {
    int idx = blockIdx.x * blockDim.x + threadIdx.x;
    if (idx >= NB * HW) return;
    float s = 0.f;
    #pragma unroll
    for (int k = 0; k < 24; k++) s += g_fpart[k * (NB * HW) + idx];
    g_fnorm[idx] = sqrtf(s);
}

// ---------------- 3. fused argmax + ordered compaction, block per n ----------------
__global__ void __launch_bounds__(1024) k_seed(const float* __restrict__ cam,
                                               const float* __restrict__ label) {
    __shared__ int spcls[HW];
    __shared__ float slab[NC];
    int n = blockIdx.x, t = threadIdx.x;
    if (t < NC) slab[t] = label[n * NC + t];
    __syncthreads();
    for (int m = t; m < HW; m += 1024) {
        const float* cp = cam + (size_t)n * NC * HW + m;
        float best = cp[0];
        int bi = 0;
        #pragma unroll
        for (int c = 1; c < NC; c++) {
            float v = cp[c * HW];
            if (v > best) { best = v; bi = c; }   // first max on ties
        }
        spcls[m] = (slab[bi] > 0.f) ? bi : -1;
    }
    __syncthreads();
    int w = t >> 5, lane = t & 31;
    if (w < NC) {
        int cnt = 0;
        int* lst = g_list + ((size_t)n * NC + w) * HW;
        for (int base = 0; base < HW; base += 32) {
            int p = spcls[base + lane];
            unsigned msk = __ballot_sync(0xffffffffu, p == w);
            if (p == w) lst[cnt + __popc(msk & ((1u << lane) - 1u))] = base + lane;
            cnt += __popc(msk);
        }
        if (!lane) g_cnt[n * NC + w] = cnt;
    }
}

// ---- 4. fused 10-iter cosine k-means: 8 warps, 2-px ILP, software-pipelined loads ----
#define KW 8   // warps per kmeans block

#define LOADPAIR(VA, VB, HAS, PI) {                                   \
    int _m0 = lst[PI];                                                \
    HAS = (PI + 1 < cnt);                                             \
    int _m1 = HAS ? lst[(PI) + 1] : _m0;                              \
    const float* _fa = fbase + (size_t)_m0 * CF + lane;               \
    const float* _fb = fbase + (size_t)_m1 * CF + lane;               \
    _Pragma("unroll")                                                 \
    for (int _j = 0; _j < 24; _j++) {                                 \
        VA[_j] = _fa[_j * 32];                                        \
        VB[_j] = _fb[_j * 32];                                        \
    } }

#define DOTPAIR(VA, VB) {                                             \
    d0a = 0.f; d1a = 0.f; d0b = 0.f; d1b = 0.f;                       \
    _Pragma("unroll")                                                 \
    for (int _j = 0; _j < 24; _j++) {                                 \
        float _c0 = cen[lane + _j * 32];                              \
        float _c1 = cen[CF + lane + _j * 32];                         \
        d0a += VA[_j] * _c0; d1a += VA[_j] * _c1;                     \
        d0b += VB[_j] * _c0; d1b += VB[_j] * _c1;                     \
    } }

#define FINPAIR(VA, VB, HAS) {                                        \
    _Pragma("unroll")                                                 \
    for (int _o = 16; _o; _o >>= 1) {                                 \
        d0a += __shfl_xor_sync(0xffffffffu, d0a, _o);                 \
        d1a += __shfl_xor_sync(0xffffffffu, d1a, _o);                 \
        d0b += __shfl_xor_sync(0xffffffffu, d0b, _o);                 \
        d1b += __shfl_xor_sync(0xffffffffu, d1b, _o);                 \
    }                                                                 \
    int _aa = (d1a * inv1 > d0a * inv0) ? 1 : 0;                      \
    int _ab = (d1b * inv1 > d0b * inv0) ? 1 : 0;                      \
    float _w0a = _aa ? 0.f : 1.f, _w1a = _aa ? 1.f : 0.f;             \
    float _w0b = 0.f, _w1b = 0.f;                                     \
    if (HAS) { _w0b = _ab ? 0.f : 1.f; _w1b = _ab ? 1.f : 0.f; }      \
    _Pragma("unroll")                                                 \
    for (int _j = 0; _j < 24; _j++) {                                 \
        acc0[_j] = fmaf(_w0a, VA[_j], fmaf(_w0b, VB[_j], acc0[_j]));  \
        acc1[_j] = fmaf(_w1a, VA[_j], fmaf(_w1b, VB[_j], acc1[_j]));  \
    }                                                                 \
    myc0 += (1 - _aa) + (HAS ? (1 - _ab) : 0);                        \
    myc1 += _aa + (HAS ? _ab : 0); }

__global__ void __launch_bounds__(32 * KW) k_kmeans() {
    extern __shared__ float buf[];
    float* cen  = buf;            // [2][CF]
    float* part = buf + 2 * CF;   // [KW][2][CF]
    __shared__ int   pcnt[KW][2];
    __shared__ float inv_s[2];
    __shared__ int   cnts[2];
    int bc = blockIdx.x;
    int n = bc / NC;
    int t = threadIdx.x, wid = t >> 5, lane = t & 31;
    int cnt = g_cnt[bc];
    float* gc = g_cent + (size_t)bc * 2 * CF;
    if (cnt < 2) {   // reference: centers forced to zero
        for (int i = t; i < 2 * CF; i += 32 * KW) gc[i] = 0.f;
        if (t < 2) g_cnorm[bc * 2 + t] = 0.f;
        return;
    }
    const int* lst = g_list + (size_t)bc * HW;
    const float* fbase = g_featT + (size_t)n * HW * CF;
    int i0 = lst[0], i1 = lst[1];
    for (int d = t; d < CF; d += 32 * KW) {
        cen[d]      = fbase[(size_t)i0 * CF + d];
        cen[CF + d] = fbase[(size_t)i1 * CF + d];
    }
    __syncthreads();

    for (int iter = 0; iter < 10; iter++) {
        if (wid < 2) {   // center inverse norms
            float s = 0.f;
            for (int d = lane; d < CF; d += 32) { float v = cen[wid * CF + d]; s += v * v; }
            #pragma unroll
            for (int o = 16; o; o >>= 1) s += __shfl_xor_sync(0xffffffffu, s, o);
            if (!lane) inv_s[wid] = 1.f / fmaxf(sqrtf(s), 1e-8f);
        }
        __syncthreads();
        float inv0 = inv_s[0], inv1 = inv_s[1];
        float acc0[24], acc1[24];
        #pragma unroll
        for (int j = 0; j < 24; j++) { acc0[j] = 0.f; acc1[j] = 0.f; }
        int myc0 = 0, myc1 = 0;

        // software-pipelined 2-pixel steps: prefetch next pair before processing current
        float vax[24], vbx[24], vay[24], vby[24];
        float d0a, d1a, d0b, d1b;
        int hasx = 0, hasy = 0;
        int pi = wid * 2;
        if (pi < cnt) LOADPAIR(vax, vbx, hasx, pi);
        while (pi < cnt) {
            int pj = pi + 2 * KW;
            if (pj < cnt) LOADPAIR(vay, vby, hasy, pj);   // prefetch
            DOTPAIR(vax, vbx);
            FINPAIR(vax, vbx, hasx);
            pi = pj;
            if (pi >= cnt) break;
            pj = pi + 2 * KW;
            if (pj < cnt) LOADPAIR(vax, vbx, hasx, pj);   // prefetch
            DOTPAIR(vay, vby);
            FINPAIR(vay, vby, hasy);
            pi = pj;
        }

        #pragma unroll
        for (int j = 0; j < 24; j++) {   // one smem dump per iteration
            part[(wid * 2 + 0) * CF + lane + j * 32] = acc0[j];
            part[(wid * 2 + 1) * CF + lane + j * 32] = acc1[j];
        }
        if (!lane) { pcnt[wid][0] = myc0; pcnt[wid][1] = myc1; }
        __syncthreads();
        if (t < 2) {
            int s = 0;
            #pragma unroll
            for (int w2 = 0; w2 < KW; w2++) s += pcnt[w2][t];
            cnts[t] = s;
        }
        __syncthreads();
        float div0 = 1.f / fmaxf((float)cnts[0], 1.f);
        float div1 = 1.f / fmaxf((float)cnts[1], 1.f);
        for (int d = t; d < CF; d += 32 * KW) {
            float s0 = 0.f, s1 = 0.f;
            #pragma unroll
            for (int w2 = 0; w2 < KW; w2++) {
                s0 += part[(w2 * 2) * CF + d];
                s1 += part[(w2 * 2 + 1) * CF + d];
            }
            cen[d] = s0 * div0;
            cen[CF + d] = s1 * div1;
        }
        __syncthreads();
    }
    for (int d = t; d < CF; d += 32 * KW) { gc[d] = cen[d]; gc[CF + d] = cen[CF + d]; }
    if (wid < 2) {
        float s = 0.f;
        for (int d = lane; d < CF; d += 32) { float v = cen[wid * CF + d]; s += v * v; }
        #pragma unroll
        for (int o = 16; o; o >>= 1) s += __shfl_xor_sync(0xffffffffu, s, o);
        if (!lane) g_cnorm[bc * 2 + wid] = sqrtf(s);
    }
}

// ---- 5. GEMM via packed f32x2 FMA: D[n][j][m] = centers[n][j].feat[n][m] ----
#define GT 48   // k-tile
__global__ void __launch_bounds__(128) k_gemm(const float* __restrict__ feat) {
    extern __shared__ float sm[];
    float* fS = sm;                                            // [GT][256]
    unsigned long long* cS2 = (unsigned long long*)(sm + GT * 256);  // [NJ][GT]
    int n = blockIdx.y, m0 = blockIdx.x * 256;
    int t = threadIdx.x;
    int p = t & 63, g = t >> 6;    // g = j-group (warp-uniform)
    unsigned long long acc[2][21];
    #pragma unroll
    for (int i = 0; i < 2; i++)
        #pragma unroll
        for (int j = 0; j < 21; j++) acc[i][j] = 0ull;

    for (int k0 = 0; k0 < CF; k0 += GT) {
        __syncthreads();
        for (int idx = t; idx < GT * 64; idx += 128) {
            int dd = idx >> 6, c4 = idx & 63;
            float4 v = *(const float4*)&feat[((size_t)(n * CF + k0 + dd)) * HW + m0 + c4 * 4];
            *(float4*)&fS[dd * 256 + c4 * 4] = v;
        }
        for (int idx = t; idx < NJ * GT; idx += 128) {
            int j = idx / GT, dd = idx % GT;
            float v = g_cent[((size_t)n * NJ + j) * CF + k0 + dd];
            float2 d2 = make_float2(v, v);
            cS2[j * GT + dd] = *(unsigned long long*)&d2;
        }
        __syncthreads();
        #pragma unroll 4
        for (int dd = 0; dd < GT; dd += 2) {
            unsigned long long a00 = *(const unsigned long long*)&fS[dd * 256 + 2 * p];
            unsigned long long a01 = *(const unsigned long long*)&fS[dd * 256 + 128 + 2 * p];
            unsigned long long a10 = *(const unsigned long long*)&fS[(dd + 1) * 256 + 2 * p];
            unsigned long long a11 = *(const unsigned long long*)&fS[(dd + 1) * 256 + 128 + 2 * p];
            #pragma unroll
            for (int j = 0; j < 21; j++) {
                ulonglong2 c2 = *(const ulonglong2*)&cS2[(g * 21 + j) * GT + dd];
                FMA_F32X2(acc[0][j], a00, c2.x);
                FMA_F32X2(acc[1][j], a01, c2.x);
                FMA_F32X2(acc[0][j], a10, c2.y);
                FMA_F32X2(acc[1][j], a11, c2.y);
            }
        }
    }
    #pragma unroll
    for (int j = 0; j < 21; j++) {
        float* dp = g_D + ((size_t)n * NJ + g * 21 + j) * HW + m0;
        *(float2*)&dp[2 * p]       = *(float2*)&acc[0][j];
        *(float2*)&dp[128 + 2 * p] = *(float2*)&acc[1][j];
    }
}

// ---------------- 6. fused cam + per-map max-normalize + Sinkhorn K matrix ----------------
__global__ void __launch_bounds__(256) k_camkmat(const float* __restrict__ label,
                                                 float* __restrict__ out) {
    __shared__ float scam[HW];
    __shared__ float red[256];
    int bc = blockIdx.x, n = bc / NC, c = bc % NC, t = threadIdx.x;
    int cnt = g_cnt[bc];
    float lab = label[bc];
    float inv_cn0 = 1.f / fmaxf(g_cnorm[n * NJ + 2 * c], 1e-8f);
    float inv_cn1 = 1.f / fmaxf(g_cnorm[n * NJ + 2 * c + 1], 1e-8f);
    float ik0 = 1.f / (g_cnorm[n * NJ + c] + 1e-5f);         // kmat quirk: j = k*21 + c
    float ik1 = 1.f / (g_cnorm[n * NJ + NC + c] + 1e-5f);
    const float* D0  = g_D + ((size_t)n * NJ + 2 * c) * HW;
    const float* D1  = D0 + HW;
    const float* Dk0 = g_D + ((size_t)n * NJ + c) * HW;
    const float* Dk1 = g_D + ((size_t)n * NJ + NC + c) * HW;
    float* Km = g_Kmat + (size_t)bc * HW * 2;
    float mx = -INFINITY;
    for (int m = t; m < HW; m += 256) {
        float fn = g_fnorm[n * HW + m];
        float camv = 0.f;
        if (cnt >= 2) {
            float fi = 1.f / fmaxf(fn, 1e-8f);
            camv = 0.5f * (D0[m] * inv_cn0 + D1[m] * inv_cn1) * fi * lab;
        }
        scam[m] = camv;
        mx = fmaxf(mx, camv);
        float fk = 1.f / (fn + 1e-5f);
        Km[m * 2 + 0] = expf((Dk0[m] * fk * ik0 - 1.f) * 10.f);
        Km[m * 2 + 1] = expf((Dk1[m] * fk * ik1 - 1.f) * 10.f);
    }
    red[t] = mx;
    __syncthreads();
    for (int s = 128; s; s >>= 1) { if (t < s) red[t] = fmaxf(red[t], red[t + s]); __syncthreads(); }
    float inv = 1.f / (red[0] + 1e-5f);
    for (int m = t; m < HW; m += 256) out[(size_t)bc * HW + m] = scam[m] * inv;
}

// ---------------- 7. Sinkhorn with faithful early stop, block per n ----------------
__global__ void __launch_bounds__(1024) k_sinkhorn(float* __restrict__ Tout) {
    __shared__ float cv[NJ], cvn[NJ];
    __shared__ float red[1024];
    __shared__ float errS;
    int n = blockIdx.x, t = threadIdx.x, lane = t & 31, wid = t >> 5;
    const float u = 1.f / (float)HW, v = 0.5f;
    float* rg = g_r + (size_t)n * NC * HW;
    const float* Km = g_Kmat + (size_t)n * NC * HW * 2;
    const float2* Km2 = (const float2*)Km;
    if (t < NJ) cv[t] = 1.f;
    for (int i = t; i < NC * HW; i += 1024) rg[i] = 1.f;
    __syncthreads();

    for (int it = 0; it < 100; it++) {
        float errp = 0.f;
        for (int i = t; i < NC * HW; i += 1024) {
            int c = i >> 12;
            float2 kk = Km2[i];
            float den = kk.x * cv[2 * c] + kk.y * cv[2 * c + 1];
            float rn = u / den;
            errp += fabsf(rn - rg[i]);
            rg[i] = rn;
        }
        red[t] = errp;
        __syncthreads();
        for (int s = 512; s; s >>= 1) { if (t < s) red[t] += red[t + s]; __syncthreads(); }
        if (!t) errS = red[0] / (float)(NC * HW);
        // c-update: warp per class, float2 loads cover both k, fully coalesced
        if (wid < NC) {
            const float2* kp = Km2 + (size_t)wid * HW;
            const float* rp = rg + wid * HW;
            float s0 = 0.f, s1 = 0.f;
            for (int m = lane; m < HW; m += 32) {
                float2 kk = kp[m];
                float rr = rp[m];
                s0 += kk.x * rr;
                s1 += kk.y * rr;
            }
            #pragma unroll
            for (int o = 16; o; o >>= 1) {
                s0 += __shfl_xor_sync(0xffffffffu, s0, o);
                s1 += __shfl_xor_sync(0xffffffffu, s1, o);
            }
            if (!lane) { cvn[2 * wid] = v / s0; cvn[2 * wid + 1] = v / s1; }
        }
        __syncthreads();
        if (t < NJ) cv[t] = cvn[t];
        __syncthreads();
        if (errS < 0.01f) break;
    }
    for (int i = t; i < NC * HW * 2; i += 1024) {
        int c = i / (2 * HW);
        int k = (i / HW) & 1;
        int m = i & (HW - 1);
        Tout[(size_t)n * NC * 2 * HW + i] =
            rg[c * HW + m] * cv[2 * c + k] * Km[(size_t)(c * HW + m) * 2 + k];
    }
}

// ---------------- launcher ----------------
extern "C" void kernel_launch(void* const* d_in, const int* in_sizes, int n_in,
                              void* d_out, int out_size) {
    const float* norm_cam = (const float*)d_in[0];   // [8,21,64,64]
    const float* label    = (const float*)d_in[1];   // [8,21,1,1]
    const float* feature  = (const float*)d_in[2];   // [8,768,64,64]
    float* out  = (float*)d_out;                     // [8,21,64,64]
    float* Tout = out + NB * NC * HW;                // [8,21,2,64,64]

    const int KMEANS_SMEM = (2 * CF + KW * 2 * CF) * sizeof(float);      // 55296 B
    const int GEMM_SMEM   = GT * 256 * 4 + NJ * GT * 8;                  // 65280 B
    cudaFuncSetAttribute(k_kmeans, cudaFuncAttributeMaxDynamicSharedMemorySize, KMEANS_SMEM);
    cudaFuncSetAttribute(k_gemm,   cudaFuncAttributeMaxDynamicSharedMemorySize, GEMM_SMEM);

    k_transpose<<<dim3(HW / 32, CF / 32, NB), dim3(32, 8)>>>(feature);
    k_fnfin   <<<(NB * HW + 255) / 256, 256>>>();
    k_seed    <<<NB, 1024>>>(norm_cam, label);
    k_kmeans  <<<NB * NC, 32 * KW, KMEANS_SMEM>>>();
    k_gemm    <<<dim3(HW / 256, NB), 128, GEMM_SMEM>>>(feature);
    k_camkmat <<<NB * NC, 256>>>(label, out);
    k_sinkhorn<<<NB, 1024>>>(Tout);
}

// round 7
// speedup vs baseline: 2.3499x; 1.2160x over previous
#include <cuda_runtime.h>
#include <math.h>

#define NB 8
#define NC 21
#define HW 4096
#define CF 768
#define NJ 42   // NC * 2

// ---------------- scratch (__device__ globals; no allocation allowed) ----------------
__device__ float g_featT[NB * HW * CF];   // [n][m][d]
__device__ float g_fpart[24 * NB * HW];   // per-d-tile partial sumsq
__device__ float g_fnorm[NB * HW];        // ||feat[n,m]||
__device__ int   g_list[NB * NC * HW];    // valid pixel indices per (n,c), ascending
__device__ int   g_cnt[NB * NC];
__device__ float g_cent[NB * NJ * CF];    // [n][c*2+k][d]
__device__ float g_cnorm[NB * NJ];
__device__ float g_D[NB * NJ * HW];       // [n][j][m] = centers[j] . feat[m]
__device__ float g_Kmat[NB * NC * HW * 2];// [n][c][m][k]
__device__ float g_r[NB * NC * HW];
__device__ float g_cv[NB * NJ];           // sinkhorn column scalings

// packed f32x2 FMA (FFMA2): d = a*b + d, lane-wise on 2 packed floats
#define FMA_F32X2(d, a, b) \
    asm("fma.rn.f32x2 %0, %1, %2, %0;" : "+l"(d) : "l"(a), "l"(b))

// ---------------- 1. transpose feature + per-column partial sumsq ----------------
__global__ void k_transpose(const float* __restrict__ feat) {
    __shared__ float tile[32][33];
    __shared__ float colp[8][33];
    int n = blockIdx.z;
    int d0 = blockIdx.y * 32, m0 = blockIdx.x * 32;
    int tx = threadIdx.x, ty = threadIdx.y;
    float acc = 0.f;
    for (int i = ty; i < 32; i += 8) {
        float v = feat[(n * CF + d0 + i) * HW + m0 + tx];
        tile[i][tx] = v;
        acc += v * v;
    }
    colp[ty][tx] = acc;
    __syncthreads();
    for (int i = ty; i < 32; i += 8)
        g_featT[((size_t)n * HW + m0 + i) * CF + d0 + tx] = tile[tx][i];
    if (ty == 0) {
        float s = 0.f;
        #pragma unroll
        for (int r = 0; r < 8; r++) s += colp[r][tx];
        g_fpart[blockIdx.y * (NB * HW) + n * HW + m0 + tx] = s;
    }
}

// ---------------- 2. finalize feature norms (deterministic 24-way sum) ----------------
__global__ void k_fnfin() {
    int idx = blockIdx.x * blockDim.x + threadIdx.x;
    if (idx >= NB * HW) return;
    float s = 0.f;
    #pragma unroll
    for (int k = 0; k < 24; k++) s += g_fpart[k * (NB * HW) + idx];
    g_fnorm[idx] = sqrtf(s);
}

// ---------------- 3. fused argmax + ordered compaction, block per n ----------------
__global__ void __launch_bounds__(1024) k_seed(const float* __restrict__ cam,
                                               const float* __restrict__ label) {
    __shared__ int spcls[HW];
    __shared__ float slab[NC];
    int n = blockIdx.x, t = threadIdx.x;
    if (t < NC) slab[t] = label[n * NC + t];
    __syncthreads();
    for (int m = t; m < HW; m += 1024) {
        const float* cp = cam + (size_t)n * NC * HW + m;
        float best = cp[0];
        int bi = 0;
        #pragma unroll
        for (int c = 1; c < NC; c++) {
            float v = cp[c * HW];
            if (v > best) { best = v; bi = c; }   // first max on ties
        }
        spcls[m] = (slab[bi] > 0.f) ? bi : -1;
    }
    __syncthreads();
    int w = t >> 5, lane = t & 31;
    if (w < NC) {
        int cnt = 0;
        int* lst = g_list + ((size_t)n * NC + w) * HW;
        for (int base = 0; base < HW; base += 32) {
            int p = spcls[base + lane];
            unsigned msk = __ballot_sync(0xffffffffu, p == w);
            if (p == w) lst[cnt + __popc(msk & ((1u << lane) - 1u))] = base + lane;
            cnt += __popc(msk);
        }
        if (!lane) g_cnt[n * NC + w] = cnt;
    }
}

// ---- 4. k-means: 8 warps, 2-px ILP, float4 loads, pipelined, convergence early-exit ----
#define KW 8   // warps per kmeans block

#define LOADPAIR(VA, VB, HAS, PI) {                                   \
    int _m0 = lst[PI];                                                \
    HAS = (PI + 1 < cnt);                                             \
    int _m1 = HAS ? lst[(PI) + 1] : _m0;                              \
    const float4* _fa = (const float4*)(fbase + (size_t)_m0 * CF) + lane; \
    const float4* _fb = (const float4*)(fbase + (size_t)_m1 * CF) + lane; \
    _Pragma("unroll")                                                 \
    for (int _j = 0; _j < 6; _j++) {                                  \
        VA[_j] = _fa[_j * 32];                                        \
        VB[_j] = _fb[_j * 32];                                        \
    } }

#define DOTPAIR(VA, VB) {                                             \
    d0a = 0.f; d1a = 0.f; d0b = 0.f; d1b = 0.f;                       \
    _Pragma("unroll")                                                 \
    for (int _j = 0; _j < 6; _j++) {                                  \
        float4 _c0 = cen4[lane + _j * 32];                            \
        float4 _c1 = cen4[48 * 4 + lane + _j * 32];                   \
        d0a += VA[_j].x * _c0.x + VA[_j].y * _c0.y                    \
             + VA[_j].z * _c0.z + VA[_j].w * _c0.w;                   \
        d1a += VA[_j].x * _c1.x + VA[_j].y * _c1.y                    \
             + VA[_j].z * _c1.z + VA[_j].w * _c1.w;                   \
        d0b += VB[_j].x * _c0.x + VB[_j].y * _c0.y                    \
             + VB[_j].z * _c0.z + VB[_j].w * _c0.w;                   \
        d1b += VB[_j].x * _c1.x + VB[_j].y * _c1.y                    \
             + VB[_j].z * _c1.z + VB[_j].w * _c1.w;                   \
    } }

#define FINPAIR(VA, VB, HAS, PI) {                                    \
    _Pragma("unroll")                                                 \
    for (int _o = 16; _o; _o >>= 1) {                                 \
        d0a += __shfl_xor_sync(0xffffffffu, d0a, _o);                 \
        d1a += __shfl_xor_sync(0xffffffffu, d1a, _o);                 \
        d0b += __shfl_xor_sync(0xffffffffu, d0b, _o);                 \
        d1b += __shfl_xor_sync(0xffffffffu, d1b, _o);                 \
    }                                                                 \
    int _aa = (d1a * inv1 > d0a * inv0) ? 1 : 0;                      \
    int _ab = (d1b * inv1 > d0b * inv0) ? 1 : 0;                      \
    if (!lane) {                                                      \
        if (iter > 0) mychg += (sprev[PI] != _aa)                     \
                             + (HAS ? (sprev[(PI) + 1] != _ab) : 0);  \
        sprev[PI] = (unsigned char)_aa;                               \
        if (HAS) sprev[(PI) + 1] = (unsigned char)_ab;                \
    }                                                                 \
    float _w0a = _aa ? 0.f : 1.f, _w1a = _aa ? 1.f : 0.f;             \
    float _w0b = 0.f, _w1b = 0.f;                                     \
    if (HAS) { _w0b = _ab ? 0.f : 1.f; _w1b = _ab ? 1.f : 0.f; }      \
    _Pragma("unroll")                                                 \
    for (int _j = 0; _j < 6; _j++) {                                  \
        acc0[_j].x = fmaf(_w0a, VA[_j].x, fmaf(_w0b, VB[_j].x, acc0[_j].x)); \
        acc0[_j].y = fmaf(_w0a, VA[_j].y, fmaf(_w0b, VB[_j].y, acc0[_j].y)); \
        acc0[_j].z = fmaf(_w0a, VA[_j].z, fmaf(_w0b, VB[_j].z, acc0[_j].z)); \
        acc0[_j].w = fmaf(_w0a, VA[_j].w, fmaf(_w0b, VB[_j].w, acc0[_j].w)); \
        acc1[_j].x = fmaf(_w1a, VA[_j].x, fmaf(_w1b, VB[_j].x, acc1[_j].x)); \
        acc1[_j].y = fmaf(_w1a, VA[_j].y, fmaf(_w1b, VB[_j].y, acc1[_j].y)); \
        acc1[_j].z = fmaf(_w1a, VA[_j].z, fmaf(_w1b, VB[_j].z, acc1[_j].z)); \
        acc1[_j].w = fmaf(_w1a, VA[_j].w, fmaf(_w1b, VB[_j].w, acc1[_j].w)); \
    }                                                                 \
    myc0 += (1 - _aa) + (HAS ? (1 - _ab) : 0);                        \
    myc1 += _aa + (HAS ? _ab : 0); }

__global__ void __launch_bounds__(32 * KW) k_kmeans() {
    extern __shared__ float buf[];
    float* cen  = buf;            // [2][CF]
    float* part = buf + 2 * CF;   // [KW][2][CF]
    float4* cen4 = (float4*)cen;
    __shared__ unsigned char sprev[HW];
    __shared__ int   pcnt[KW][2];
    __shared__ int   pchg[KW];
    __shared__ float inv_s[2];
    __shared__ int   cnts[2], schg;
    int bc = blockIdx.x;
    int n = bc / NC;
    int t = threadIdx.x, wid = t >> 5, lane = t & 31;
    int cnt = g_cnt[bc];
    float* gc = g_cent + (size_t)bc * 2 * CF;
    if (cnt < 2) {   // reference: centers forced to zero
        for (int i = t; i < 2 * CF; i += 32 * KW) gc[i] = 0.f;
        if (t < 2) g_cnorm[bc * 2 + t] = 0.f;
        return;
    }
    const int* lst = g_list + (size_t)bc * HW;
    const float* fbase = g_featT + (size_t)n * HW * CF;
    int i0 = lst[0], i1 = lst[1];
    for (int d = t; d < CF; d += 32 * KW) {
        cen[d]      = fbase[(size_t)i0 * CF + d];
        cen[CF + d] = fbase[(size_t)i1 * CF + d];
    }
    __syncthreads();

    for (int iter = 0; iter < 10; iter++) {
        if (wid < 2) {   // center inverse norms
            float s = 0.f;
            for (int d = lane; d < CF; d += 32) { float v = cen[wid * CF + d]; s += v * v; }
            #pragma unroll
            for (int o = 16; o; o >>= 1) s += __shfl_xor_sync(0xffffffffu, s, o);
            if (!lane) inv_s[wid] = 1.f / fmaxf(sqrtf(s), 1e-8f);
        }
        __syncthreads();
        float inv0 = inv_s[0], inv1 = inv_s[1];
        float4 acc0[6], acc1[6];
        #pragma unroll
        for (int j = 0; j < 6; j++) {
            acc0[j] = make_float4(0.f, 0.f, 0.f, 0.f);
            acc1[j] = make_float4(0.f, 0.f, 0.f, 0.f);
        }
        int myc0 = 0, myc1 = 0, mychg = 0;

        // software-pipelined 2-pixel steps with next-pair prefetch
        float4 vax[6], vbx[6], vay[6], vby[6];
        float d0a, d1a, d0b, d1b;
        int hasx = 0, hasy = 0;
        int pi = wid * 2;
        if (pi < cnt) LOADPAIR(vax, vbx, hasx, pi);
        while (pi < cnt) {
            int pj = pi + 2 * KW;
            if (pj < cnt) LOADPAIR(vay, vby, hasy, pj);
            DOTPAIR(vax, vbx);
            FINPAIR(vax, vbx, hasx, pi);
            pi = pj;
            if (pi >= cnt) break;
            pj = pi + 2 * KW;
            if (pj < cnt) LOADPAIR(vax, vbx, hasx, pj);
            DOTPAIR(vay, vby);
            FINPAIR(vay, vby, hasy, pi);
            pi = pj;
        }

        float4* p0 = (float4*)&part[(wid * 2 + 0) * CF];
        float4* p1 = (float4*)&part[(wid * 2 + 1) * CF];
        #pragma unroll
        for (int j = 0; j < 6; j++) {   // one smem dump per iteration
            p0[lane + j * 32] = acc0[j];
            p1[lane + j * 32] = acc1[j];
        }
        if (!lane) { pcnt[wid][0] = myc0; pcnt[wid][1] = myc1; pchg[wid] = mychg; }
        __syncthreads();
        if (t < 2) {
            int s = 0;
            #pragma unroll
            for (int w2 = 0; w2 < KW; w2++) s += pcnt[w2][t];
            cnts[t] = s;
        }
        if (t == 2) {
            int s = 0;
            #pragma unroll
            for (int w2 = 0; w2 < KW; w2++) s += pchg[w2];
            schg = s;
        }
        __syncthreads();
        float div0 = 1.f / fmaxf((float)cnts[0], 1.f);
        float div1 = 1.f / fmaxf((float)cnts[1], 1.f);
        for (int d = t; d < CF; d += 32 * KW) {
            float s0 = 0.f, s1 = 0.f;
            #pragma unroll
            for (int w2 = 0; w2 < KW; w2++) {
                s0 += part[(w2 * 2) * CF + d];
                s1 += part[(w2 * 2 + 1) * CF + d];
            }
            cen[d] = s0 * div0;
            cen[CF + d] = s1 * div1;
        }
        __syncthreads();
        // assignments identical to previous iteration -> fixed point; rest are no-ops
        if (iter > 0 && schg == 0) break;
    }
    for (int d = t; d < CF; d += 32 * KW) { gc[d] = cen[d]; gc[CF + d] = cen[CF + d]; }
    if (wid < 2) {
        float s = 0.f;
        for (int d = lane; d < CF; d += 32) { float v = cen[wid * CF + d]; s += v * v; }
        #pragma unroll
        for (int o = 16; o; o >>= 1) s += __shfl_xor_sync(0xffffffffu, s, o);
        if (!lane) g_cnorm[bc * 2 + wid] = sqrtf(s);
    }
}

// ---- 5. GEMM via packed f32x2 FMA: D[n][j][m] = centers[n][j].feat[n][m] ----
#define GT 48   // k-tile
__global__ void __launch_bounds__(128) k_gemm(const float* __restrict__ feat) {
    extern __shared__ float sm[];
    float* fS = sm;                                            // [GT][256]
    unsigned long long* cS2 = (unsigned long long*)(sm + GT * 256);  // [NJ][GT]
    int n = blockIdx.y, m0 = blockIdx.x * 256;
    int t = threadIdx.x;
    int p = t & 63, g = t >> 6;    // g = j-group (warp-uniform)
    unsigned long long acc[2][21];
    #pragma unroll
    for (int i = 0; i < 2; i++)
        #pragma unroll
        for (int j = 0; j < 21; j++) acc[i][j] = 0ull;

    for (int k0 = 0; k0 < CF; k0 += GT) {
        __syncthreads();
        for (int idx = t; idx < GT * 64; idx += 128) {
            int dd = idx >> 6, c4 = idx & 63;
            float4 v = *(const float4*)&feat[((size_t)(n * CF + k0 + dd)) * HW + m0 + c4 * 4];
            *(float4*)&fS[dd * 256 + c4 * 4] = v;
        }
        for (int idx = t; idx < NJ * GT; idx += 128) {
            int j = idx / GT, dd = idx % GT;
            float v = g_cent[((size_t)n * NJ + j) * CF + k0 + dd];
            float2 d2 = make_float2(v, v);
            cS2[j * GT + dd] = *(unsigned long long*)&d2;
        }
        __syncthreads();
        #pragma unroll 4
        for (int dd = 0; dd < GT; dd += 2) {
            unsigned long long a00 = *(const unsigned long long*)&fS[dd * 256 + 2 * p];
            unsigned long long a01 = *(const unsigned long long*)&fS[dd * 256 + 128 + 2 * p];
            unsigned long long a10 = *(const unsigned long long*)&fS[(dd + 1) * 256 + 2 * p];
            unsigned long long a11 = *(const unsigned long long*)&fS[(dd + 1) * 256 + 128 + 2 * p];
            #pragma unroll
            for (int j = 0; j < 21; j++) {
                ulonglong2 c2 = *(const ulonglong2*)&cS2[(g * 21 + j) * GT + dd];
                FMA_F32X2(acc[0][j], a00, c2.x);
                FMA_F32X2(acc[1][j], a01, c2.x);
                FMA_F32X2(acc[0][j], a10, c2.y);
                FMA_F32X2(acc[1][j], a11, c2.y);
            }
        }
    }
    #pragma unroll
    for (int j = 0; j < 21; j++) {
        float* dp = g_D + ((size_t)n * NJ + g * 21 + j) * HW + m0;
        *(float2*)&dp[2 * p]       = *(float2*)&acc[0][j];
        *(float2*)&dp[128 + 2 * p] = *(float2*)&acc[1][j];
    }
}

// ---------------- 6. fused cam + per-map max-normalize + Sinkhorn K matrix ----------------
__global__ void __launch_bounds__(256) k_camkmat(const float* __restrict__ label,
                                                 float* __restrict__ out) {
    __shared__ float scam[HW];
    __shared__ float red[256];
    int bc = blockIdx.x, n = bc / NC, c = bc % NC, t = threadIdx.x;
    int cnt = g_cnt[bc];
    float lab = label[bc];
    float inv_cn0 = 1.f / fmaxf(g_cnorm[n * NJ + 2 * c], 1e-8f);
    float inv_cn1 = 1.f / fmaxf(g_cnorm[n * NJ + 2 * c + 1], 1e-8f);
    float ik0 = 1.f / (g_cnorm[n * NJ + c] + 1e-5f);         // kmat quirk: j = k*21 + c
    float ik1 = 1.f / (g_cnorm[n * NJ + NC + c] + 1e-5f);
    const float* D0  = g_D + ((size_t)n * NJ + 2 * c) * HW;
    const float* D1  = D0 + HW;
    const float* Dk0 = g_D + ((size_t)n * NJ + c) * HW;
    const float* Dk1 = g_D + ((size_t)n * NJ + NC + c) * HW;
    float* Km = g_Kmat + (size_t)bc * HW * 2;
    float mx = -INFINITY;
    for (int m = t; m < HW; m += 256) {
        float fn = g_fnorm[n * HW + m];
        float camv = 0.f;
        if (cnt >= 2) {
            float fi = 1.f / fmaxf(fn, 1e-8f);
            camv = 0.5f * (D0[m] * inv_cn0 + D1[m] * inv_cn1) * fi * lab;
        }
        scam[m] = camv;
        mx = fmaxf(mx, camv);
        float fk = 1.f / (fn + 1e-5f);
        Km[m * 2 + 0] = __expf((Dk0[m] * fk * ik0 - 1.f) * 10.f);
        Km[m * 2 + 1] = __expf((Dk1[m] * fk * ik1 - 1.f) * 10.f);
    }
    red[t] = mx;
    __syncthreads();
    for (int s = 128; s; s >>= 1) { if (t < s) red[t] = fmaxf(red[t], red[t + s]); __syncthreads(); }
    float inv = 1.f / (red[0] + 1e-5f);
    for (int m = t; m < HW; m += 256) out[(size_t)bc * HW + m] = scam[m] * inv;
}

// ---------------- 7. Sinkhorn r/c iterations with faithful early stop, block per n --------
__global__ void __launch_bounds__(1024) k_sinkhorn() {
    __shared__ float cv[NJ], cvn[NJ];
    __shared__ float red[1024];
    __shared__ float errS;
    int n = blockIdx.x, t = threadIdx.x, lane = t & 31, wid = t >> 5;
    const float u = 1.f / (float)HW, v = 0.5f;
    float* rg = g_r + (size_t)n * NC * HW;
    const float2* Km2 = (const float2*)(g_Kmat + (size_t)n * NC * HW * 2);
    const float4* Km4 = (const float4*)Km2;
    if (t < NJ) cv[t] = 1.f;
    for (int i = t; i < NC * HW; i += 1024) rg[i] = 1.f;
    __syncthreads();

    for (int it = 0; it < 100; it++) {
        float errp = 0.f;
        for (int i2 = t; i2 < NC * HW / 2; i2 += 1024) {   // 2 pixels per float4
            int i = i2 * 2;
            int c = i >> 12;
            float4 kk = Km4[i2];
            float c0 = cv[2 * c], c1 = cv[2 * c + 1];
            float rn0 = u / (kk.x * c0 + kk.y * c1);
            float rn1 = u / (kk.z * c0 + kk.w * c1);
            errp += fabsf(rn0 - rg[i]) + fabsf(rn1 - rg[i + 1]);
            rg[i] = rn0; rg[i + 1] = rn1;
        }
        red[t] = errp;
        __syncthreads();
        for (int s = 512; s; s >>= 1) { if (t < s) red[t] += red[t + s]; __syncthreads(); }
        if (!t) errS = red[0] / (float)(NC * HW);
        // c-update: warp per class, float2 loads cover both k, fully coalesced
        if (wid < NC) {
            const float2* kp = Km2 + (size_t)wid * HW;
            const float* rp = rg + wid * HW;
            float s0 = 0.f, s1 = 0.f;
            for (int m = lane; m < HW; m += 32) {
                float2 kk = kp[m];
                float rr = rp[m];
                s0 += kk.x * rr;
                s1 += kk.y * rr;
            }
            #pragma unroll
            for (int o = 16; o; o >>= 1) {
                s0 += __shfl_xor_sync(0xffffffffu, s0, o);
                s1 += __shfl_xor_sync(0xffffffffu, s1, o);
            }
            if (!lane) { cvn[2 * wid] = v / s0; cvn[2 * wid + 1] = v / s1; }
        }
        __syncthreads();
        if (t < NJ) cv[t] = cvn[t];
        __syncthreads();
        if (errS < 0.01f) break;
    }
    if (t < NJ) g_cv[n * NJ + t] = cv[t];
}

// ---------------- 8. T output: full-chip elementwise r*c*K, block per (n,c) ----------------
__global__ void __launch_bounds__(256) k_tout(float* __restrict__ Tout) {
    int bc = blockIdx.x, n = bc / NC, c = bc % NC, t = threadIdx.x;
    const float2* Km2 = (const float2*)g_Kmat + (size_t)bc * HW;
    const float* rp = g_r + (size_t)bc * HW;
    float cv0 = g_cv[n * NJ + 2 * c], cv1 = g_cv[n * NJ + 2 * c + 1];
    float* T0 = Tout + (size_t)bc * 2 * HW;   // [n][c][k=0][m]
    float* T1 = T0 + HW;                      // [n][c][k=1][m]
    for (int m = t; m < HW; m += 256) {
        float2 kk = Km2[m];
        float r = rp[m];
        T0[m] = r * cv0 * kk.x;
        T1[m] = r * cv1 * kk.y;
    }
}

// ---------------- launcher ----------------
extern "C" void kernel_launch(void* const* d_in, const int* in_sizes, int n_in,
                              void* d_out, int out_size) {
    const float* norm_cam = (const float*)d_in[0];   // [8,21,64,64]
    const float* label    = (const float*)d_in[1];   // [8,21,1,1]
    const float* feature  = (const float*)d_in[2];   // [8,768,64,64]
    float* out  = (float*)d_out;                     // [8,21,64,64]
    float* Tout = out + NB * NC * HW;                // [8,21,2,64,64]

    const int KMEANS_SMEM = (2 * CF + KW * 2 * CF) * sizeof(float);      // 55296 B
    const int GEMM_SMEM   = GT * 256 * 4 + NJ * GT * 8;                  // 65280 B
    cudaFuncSetAttribute(k_kmeans, cudaFuncAttributeMaxDynamicSharedMemorySize, KMEANS_SMEM);
    cudaFuncSetAttribute(k_gemm,   cudaFuncAttributeMaxDynamicSharedMemorySize, GEMM_SMEM);

    k_transpose<<<dim3(HW / 32, CF / 32, NB), dim3(32, 8)>>>(feature);
    k_fnfin   <<<(NB * HW + 255) / 256, 256>>>();
    k_seed    <<<NB, 1024>>>(norm_cam, label);
    k_kmeans  <<<NB * NC, 32 * KW, KMEANS_SMEM>>>();
    k_gemm    <<<dim3(HW / 256, NB), 128, GEMM_SMEM>>>(feature);
    k_camkmat <<<NB * NC, 256>>>(label, out);
    k_sinkhorn<<<NB, 1024>>>();
    k_tout    <<<NB * NC, 256>>>(Tout);
}

// round 8
// speedup vs baseline: 2.6250x; 1.1171x over previous
#include <cuda_runtime.h>
#include <math.h>

#define NB 8
#define NC 21
#define HW 4096
#define CF 768
#define NJ 42   // NC * 2

// ---------------- scratch (__device__ globals; no allocation allowed) ----------------
__device__ float g_featT[NB * HW * CF];   // [n][m][d]
__device__ float g_fpart[24 * NB * HW];   // per-d-tile partial sumsq
__device__ float g_fnorm[NB * HW];        // ||feat[n,m]||
__device__ int   g_pcls[NB * HW];         // class of pixel if valid else -1
__device__ int   g_list[NB * NC * HW];    // valid pixel indices per (n,c), ascending
__device__ int   g_cnt[NB * NC];
__device__ float g_cent[NB * NJ * CF];    // [n][c*2+k][d]
__device__ float g_cnorm[NB * NJ];
__device__ float g_D[NB * NJ * HW];       // [n][j][m] = centers[j] . feat[m]
__device__ float g_Kmat[NB * NC * HW * 2];// [n][c][m][k]
__device__ float g_r[NB * NC * HW];
__device__ float g_cv[NB * NJ];           // sinkhorn column scalings

// packed f32x2 FMA (FFMA2): d = a*b + d, lane-wise on 2 packed floats
#define FMA_F32X2(d, a, b) \
    asm("fma.rn.f32x2 %0, %1, %2, %0;" : "+l"(d) : "l"(a), "l"(b))

// ---------------- 1. transpose feature + per-column partial sumsq ----------------
__global__ void k_transpose(const float* __restrict__ feat) {
    __shared__ float tile[32][33];
    __shared__ float colp[8][33];
    int n = blockIdx.z;
    int d0 = blockIdx.y * 32, m0 = blockIdx.x * 32;
    int tx = threadIdx.x, ty = threadIdx.y;
    float acc = 0.f;
    for (int i = ty; i < 32; i += 8) {
        float v = feat[(n * CF + d0 + i) * HW + m0 + tx];
        tile[i][tx] = v;
        acc += v * v;
    }
    colp[ty][tx] = acc;
    __syncthreads();
    for (int i = ty; i < 32; i += 8)
        g_featT[((size_t)n * HW + m0 + i) * CF + d0 + tx] = tile[tx][i];
    if (ty == 0) {
        float s = 0.f;
        #pragma unroll
        for (int r = 0; r < 8; r++) s += colp[r][tx];
        g_fpart[blockIdx.y * (NB * HW) + n * HW + m0 + tx] = s;
    }
}

// ---------------- 2. finalize feature norms (deterministic 24-way sum) ----------------
__global__ void k_fnfin() {
    int idx = blockIdx.x * blockDim.x + threadIdx.x;
    if (idx >= NB * HW) return;
    float s = 0.f;
    #pragma unroll
    for (int k = 0; k < 24; k++) s += g_fpart[k * (NB * HW) + idx];
    g_fnorm[idx] = sqrtf(s);
}

// ---------------- 3a. per-pixel argmax class, full-chip elementwise ----------------
__global__ void k_argmax(const float* __restrict__ cam, const float* __restrict__ label) {
    int idx = blockIdx.x * blockDim.x + threadIdx.x;
    if (idx >= NB * HW) return;
    int n = idx >> 12, m = idx & (HW - 1);
    const float* cp = cam + (size_t)n * NC * HW + m;
    float best = cp[0];
    int bi = 0;
    #pragma unroll
    for (int c = 1; c < NC; c++) {
        float v = cp[c * HW];
        if (v > best) { best = v; bi = c; }   // first max on ties
    }
    g_pcls[idx] = (label[n * NC + bi] > 0.f) ? bi : -1;
}

// ---------------- 3b. ordered compaction in smem, block per n (21 warps) ----------------
__global__ void __launch_bounds__(672) k_lists() {
    __shared__ int spcls[HW];
    int n = blockIdx.x, t = threadIdx.x;
    for (int m = t; m < HW; m += 672) spcls[m] = g_pcls[n * HW + m];
    __syncthreads();
    int w = t >> 5, lane = t & 31;   // w in 0..20
    int cnt = 0;
    int* lst = g_list + ((size_t)n * NC + w) * HW;
    for (int base = 0; base < HW; base += 32) {
        int p = spcls[base + lane];
        unsigned msk = __ballot_sync(0xffffffffu, p == w);
        if (p == w) lst[cnt + __popc(msk & ((1u << lane) - 1u))] = base + lane;
        cnt += __popc(msk);
    }
    if (!lane) g_cnt[n * NC + w] = cnt;
}

// ---- 4. k-means: 8 warps, 2-px ILP, float4 loads, pipelined, convergence early-exit ----
#define KW 8   // warps per kmeans block

#define LOADPAIR(VA, VB, HAS, PI) {                                   \
    int _m0 = lst[PI];                                                \
    HAS = (PI + 1 < cnt);                                             \
    int _m1 = HAS ? lst[(PI) + 1] : _m0;                              \
    const float4* _fa = (const float4*)(fbase + (size_t)_m0 * CF) + lane; \
    const float4* _fb = (const float4*)(fbase + (size_t)_m1 * CF) + lane; \
    _Pragma("unroll")                                                 \
    for (int _j = 0; _j < 6; _j++) {                                  \
        VA[_j] = _fa[_j * 32];                                        \
        VB[_j] = _fb[_j * 32];                                        \
    } }

#define DOTPAIR(VA, VB) {                                             \
    d0a = 0.f; d1a = 0.f; d0b = 0.f; d1b = 0.f;                       \
    _Pragma("unroll")                                                 \
    for (int _j = 0; _j < 6; _j++) {                                  \
        float4 _c0 = cen4[lane + _j * 32];                            \
        float4 _c1 = cen4[48 * 4 + lane + _j * 32];                   \
        d0a += VA[_j].x * _c0.x + VA[_j].y * _c0.y                    \
             + VA[_j].z * _c0.z + VA[_j].w * _c0.w;                   \
        d1a += VA[_j].x * _c1.x + VA[_j].y * _c1.y                    \
             + VA[_j].z * _c1.z + VA[_j].w * _c1.w;                   \
        d0b += VB[_j].x * _c0.x + VB[_j].y * _c0.y                    \
             + VB[_j].z * _c0.z + VB[_j].w * _c0.w;                   \
        d1b += VB[_j].x * _c1.x + VB[_j].y * _c1.y                    \
             + VB[_j].z * _c1.z + VB[_j].w * _c1.w;                   \
    } }

#define FINPAIR(VA, VB, HAS, PI) {                                    \
    _Pragma("unroll")                                                 \
    for (int _o = 16; _o; _o >>= 1) {                                 \
        d0a += __shfl_xor_sync(0xffffffffu, d0a, _o);                 \
        d1a += __shfl_xor_sync(0xffffffffu, d1a, _o);                 \
        d0b += __shfl_xor_sync(0xffffffffu, d0b, _o);                 \
        d1b += __shfl_xor_sync(0xffffffffu, d1b, _o);                 \
    }                                                                 \
    int _aa = (d1a * inv1 > d0a * inv0) ? 1 : 0;                      \
    int _ab = (d1b * inv1 > d0b * inv0) ? 1 : 0;                      \
    if (!lane) {                                                      \
        if (iter > 0) mychg += (sprev[PI] != _aa)                     \
                             + (HAS ? (sprev[(PI) + 1] != _ab) : 0);  \
        sprev[PI] = (unsigned char)_aa;                               \
        if (HAS) sprev[(PI) + 1] = (unsigned char)_ab;                \
    }                                                                 \
    float _w0a = _aa ? 0.f : 1.f, _w1a = _aa ? 1.f : 0.f;             \
    float _w0b = 0.f, _w1b = 0.f;                                     \
    if (HAS) { _w0b = _ab ? 0.f : 1.f; _w1b = _ab ? 1.f : 0.f; }      \
    _Pragma("unroll")                                                 \
    for (int _j = 0; _j < 6; _j++) {                                  \
        acc0[_j].x = fmaf(_w0a, VA[_j].x, fmaf(_w0b, VB[_j].x, acc0[_j].x)); \
        acc0[_j].y = fmaf(_w0a, VA[_j].y, fmaf(_w0b, VB[_j].y, acc0[_j].y)); \
        acc0[_j].z = fmaf(_w0a, VA[_j].z, fmaf(_w0b, VB[_j].z, acc0[_j].z)); \
        acc0[_j].w = fmaf(_w0a, VA[_j].w, fmaf(_w0b, VB[_j].w, acc0[_j].w)); \
        acc1[_j].x = fmaf(_w1a, VA[_j].x, fmaf(_w1b, VB[_j].x, acc1[_j].x)); \
        acc1[_j].y = fmaf(_w1a, VA[_j].y, fmaf(_w1b, VB[_j].y, acc1[_j].y)); \
        acc1[_j].z = fmaf(_w1a, VA[_j].z, fmaf(_w1b, VB[_j].z, acc1[_j].z)); \
        acc1[_j].w = fmaf(_w1a, VA[_j].w, fmaf(_w1b, VB[_j].w, acc1[_j].w)); \
    }                                                                 \
    myc0 += (1 - _aa) + (HAS ? (1 - _ab) : 0);                        \
    myc1 += _aa + (HAS ? _ab : 0); }

__global__ void __launch_bounds__(32 * KW) k_kmeans() {
    extern __shared__ float buf[];
    float* cen  = buf;            // [2][CF]
    float* part = buf + 2 * CF;   // [KW][2][CF]
    float4* cen4 = (float4*)cen;
    __shared__ unsigned char sprev[HW];
    __shared__ int   pcnt[KW][2];
    __shared__ int   pchg[KW];
    __shared__ float inv_s[2];
    __shared__ int   cnts[2], schg;
    int bc = blockIdx.x;
    int n = bc / NC;
    int t = threadIdx.x, wid = t >> 5, lane = t & 31;
    int cnt = g_cnt[bc];
    float* gc = g_cent + (size_t)bc * 2 * CF;
    if (cnt < 2) {   // reference: centers forced to zero
        for (int i = t; i < 2 * CF; i += 32 * KW) gc[i] = 0.f;
        if (t < 2) g_cnorm[bc * 2 + t] = 0.f;
        return;
    }
    const int* lst = g_list + (size_t)bc * HW;
    const float* fbase = g_featT + (size_t)n * HW * CF;
    int i0 = lst[0], i1 = lst[1];
    for (int d = t; d < CF; d += 32 * KW) {
        cen[d]      = fbase[(size_t)i0 * CF + d];
        cen[CF + d] = fbase[(size_t)i1 * CF + d];
    }
    __syncthreads();

    for (int iter = 0; iter < 10; iter++) {
        if (wid < 2) {   // center inverse norms
            float s = 0.f;
            for (int d = lane; d < CF; d += 32) { float v = cen[wid * CF + d]; s += v * v; }
            #pragma unroll
            for (int o = 16; o; o >>= 1) s += __shfl_xor_sync(0xffffffffu, s, o);
            if (!lane) inv_s[wid] = 1.f / fmaxf(sqrtf(s), 1e-8f);
        }
        __syncthreads();
        float inv0 = inv_s[0], inv1 = inv_s[1];
        float4 acc0[6], acc1[6];
        #pragma unroll
        for (int j = 0; j < 6; j++) {
            acc0[j] = make_float4(0.f, 0.f, 0.f, 0.f);
            acc1[j] = make_float4(0.f, 0.f, 0.f, 0.f);
        }
        int myc0 = 0, myc1 = 0, mychg = 0;

        // software-pipelined 2-pixel steps with next-pair prefetch
        float4 vax[6], vbx[6], vay[6], vby[6];
        float d0a, d1a, d0b, d1b;
        int hasx = 0, hasy = 0;
        int pi = wid * 2;
        if (pi < cnt) LOADPAIR(vax, vbx, hasx, pi);
        while (pi < cnt) {
            int pj = pi + 2 * KW;
            if (pj < cnt) LOADPAIR(vay, vby, hasy, pj);
            DOTPAIR(vax, vbx);
            FINPAIR(vax, vbx, hasx, pi);
            pi = pj;
            if (pi >= cnt) break;
            pj = pi + 2 * KW;
            if (pj < cnt) LOADPAIR(vax, vbx, hasx, pj);
            DOTPAIR(vay, vby);
            FINPAIR(vay, vby, hasy, pi);
            pi = pj;
        }

        float4* p0 = (float4*)&part[(wid * 2 + 0) * CF];
        float4* p1 = (float4*)&part[(wid * 2 + 1) * CF];
        #pragma unroll
        for (int j = 0; j < 6; j++) {   // one smem dump per iteration
            p0[lane + j * 32] = acc0[j];
            p1[lane + j * 32] = acc1[j];
        }
        if (!lane) { pcnt[wid][0] = myc0; pcnt[wid][1] = myc1; pchg[wid] = mychg; }
        __syncthreads();
        if (t < 2) {
            int s = 0;
            #pragma unroll
            for (int w2 = 0; w2 < KW; w2++) s += pcnt[w2][t];
            cnts[t] = s;
        }
        if (t == 2) {
            int s = 0;
            #pragma unroll
            for (int w2 = 0; w2 < KW; w2++) s += pchg[w2];
            schg = s;
        }
        __syncthreads();
        float div0 = 1.f / fmaxf((float)cnts[0], 1.f);
        float div1 = 1.f / fmaxf((float)cnts[1], 1.f);
        for (int d = t; d < CF; d += 32 * KW) {
            float s0 = 0.f, s1 = 0.f;
            #pragma unroll
            for (int w2 = 0; w2 < KW; w2++) {
                s0 += part[(w2 * 2) * CF + d];
                s1 += part[(w2 * 2 + 1) * CF + d];
            }
            cen[d] = s0 * div0;
            cen[CF + d] = s1 * div1;
        }
        __syncthreads();
        // assignments identical to previous iteration -> fixed point; rest are no-ops
        if (iter > 0 && schg == 0) break;
    }
    for (int d = t; d < CF; d += 32 * KW) { gc[d] = cen[d]; gc[CF + d] = cen[CF + d]; }
    if (wid < 2) {
        float s = 0.f;
        for (int d = lane; d < CF; d += 32) { float v = cen[wid * CF + d]; s += v * v; }
        #pragma unroll
        for (int o = 16; o; o >>= 1) s += __shfl_xor_sync(0xffffffffu, s, o);
        if (!lane) g_cnorm[bc * 2 + wid] = sqrtf(s);
    }
}

// ---- 5. GEMM via packed f32x2 FMA, 256 threads: D[n][j][m] = centers[n][j].feat[n][m] ----
#define GT 48   // k-tile
__global__ void __launch_bounds__(256) k_gemm(const float* __restrict__ feat) {
    extern __shared__ float sm[];
    float* fS = sm;                                            // [GT][256]
    unsigned long long* cS2 = (unsigned long long*)(sm + GT * 256);  // [NJ][GT]
    int n = blockIdx.y, m0 = blockIdx.x * 256;
    int t = threadIdx.x;
    int p = t & 127, g = t >> 7;    // g = j-group (warp-uniform)
    unsigned long long acc[21];
    #pragma unroll
    for (int j = 0; j < 21; j++) acc[j] = 0ull;

    for (int k0 = 0; k0 < CF; k0 += GT) {
        __syncthreads();
        for (int idx = t; idx < GT * 64; idx += 256) {
            int dd = idx >> 6, c4 = idx & 63;
            float4 v = *(const float4*)&feat[((size_t)(n * CF + k0 + dd)) * HW + m0 + c4 * 4];
            *(float4*)&fS[dd * 256 + c4 * 4] = v;
        }
        for (int idx = t; idx < NJ * GT; idx += 256) {
            int j = idx / GT, dd = idx % GT;
            float v = g_cent[((size_t)n * NJ + j) * CF + k0 + dd];
            float2 d2 = make_float2(v, v);
            cS2[j * GT + dd] = *(unsigned long long*)&d2;
        }
        __syncthreads();
        #pragma unroll 4
        for (int dd = 0; dd < GT; dd += 2) {
            unsigned long long a0 = *(const unsigned long long*)&fS[dd * 256 + 2 * p];
            unsigned long long a1 = *(const unsigned long long*)&fS[(dd + 1) * 256 + 2 * p];
            #pragma unroll
            for (int j = 0; j < 21; j++) {
                ulonglong2 c2 = *(const ulonglong2*)&cS2[(g * 21 + j) * GT + dd];
                FMA_F32X2(acc[j], a0, c2.x);
                FMA_F32X2(acc[j], a1, c2.y);
            }
        }
    }
    #pragma unroll
    for (int j = 0; j < 21; j++) {
        float* dp = g_D + ((size_t)n * NJ + g * 21 + j) * HW + m0;
        *(float2*)&dp[2 * p] = *(float2*)&acc[j];
    }
}

// ---------------- 6. fused cam + per-map max-normalize + Sinkhorn K matrix ----------------
__global__ void __launch_bounds__(256) k_camkmat(const float* __restrict__ label,
                                                 float* __restrict__ out) {
    __shared__ float scam[HW];
    __shared__ float red[256];
    int bc = blockIdx.x, n = bc / NC, c = bc % NC, t = threadIdx.x;
    int cnt = g_cnt[bc];
    float lab = label[bc];
    float inv_cn0 = 1.f / fmaxf(g_cnorm[n * NJ + 2 * c], 1e-8f);
    float inv_cn1 = 1.f / fmaxf(g_cnorm[n * NJ + 2 * c + 1], 1e-8f);
    float ik0 = 1.f / (g_cnorm[n * NJ + c] + 1e-5f);         // kmat quirk: j = k*21 + c
    float ik1 = 1.f / (g_cnorm[n * NJ + NC + c] + 1e-5f);
    const float* D0  = g_D + ((size_t)n * NJ + 2 * c) * HW;
    const float* D1  = D0 + HW;
    const float* Dk0 = g_D + ((size_t)n * NJ + c) * HW;
    const float* Dk1 = g_D + ((size_t)n * NJ + NC + c) * HW;
    float2* Km2 = (float2*)(g_Kmat + (size_t)bc * HW * 2);
    float mx = -INFINITY;
    for (int m = t; m < HW; m += 256) {
        float fn = g_fnorm[n * HW + m];
        float camv = 0.f;
        if (cnt >= 2) {
            float fi = 1.f / fmaxf(fn, 1e-8f);
            camv = 0.5f * (D0[m] * inv_cn0 + D1[m] * inv_cn1) * fi * lab;
        }
        scam[m] = camv;
        mx = fmaxf(mx, camv);
        float fk = 1.f / (fn + 1e-5f);
        float2 kk;
        kk.x = __expf((Dk0[m] * fk * ik0 - 1.f) * 10.f);
        kk.y = __expf((Dk1[m] * fk * ik1 - 1.f) * 10.f);
        Km2[m] = kk;
    }
    red[t] = mx;
    __syncthreads();
    for (int s = 128; s; s >>= 1) { if (t < s) red[t] = fmaxf(red[t], red[t + s]); __syncthreads(); }
    float inv = 1.f / (red[0] + 1e-5f);
    for (int m = t; m < HW; m += 256) out[(size_t)bc * HW + m] = scam[m] * inv;
}

// ---- 7. Sinkhorn, fused r+c single pass per iteration, faithful early stop, block per n ----
__global__ void __launch_bounds__(1024) k_sinkhorn() {
    __shared__ float cv[NJ];
    __shared__ float spart[NC][32][2];
    __shared__ float red[1024];
    __shared__ float errS;
    int n = blockIdx.x, t = threadIdx.x, lane = t & 31, wid = t >> 5;
    const float u = 1.f / (float)HW, v = 0.5f;
    float* rg = g_r + (size_t)n * NC * HW;
    const float4* Km4 = (const float4*)(g_Kmat + (size_t)n * NC * HW * 2);
    if (t < NJ) cv[t] = 1.f;
    for (int i = t; i < NC * HW; i += 1024) rg[i] = 1.f;
    __syncthreads();

    for (int it = 0; it < 100; it++) {
        float errp = 0.f;
        // fused pass: r = u/(K@c_old) and per-class partials of K^T@r_new
        for (int c = 0; c < NC; c++) {
            float c0 = cv[2 * c], c1 = cv[2 * c + 1];
            float s0 = 0.f, s1 = 0.f;
            #pragma unroll
            for (int st = 0; st < 2; st++) {
                int i2 = t + (2 * c + st) * 1024;   // class(i2*2) == c for all t
                int i = 2 * i2;
                float4 kk = Km4[i2];
                float rn0 = u / (kk.x * c0 + kk.y * c1);
                float rn1 = u / (kk.z * c0 + kk.w * c1);
                errp += fabsf(rn0 - rg[i]) + fabsf(rn1 - rg[i + 1]);
                rg[i] = rn0; rg[i + 1] = rn1;
                s0 += kk.x * rn0 + kk.z * rn1;
                s1 += kk.y * rn0 + kk.w * rn1;
            }
            #pragma unroll
            for (int o = 16; o; o >>= 1) {
                s0 += __shfl_xor_sync(0xffffffffu, s0, o);
                s1 += __shfl_xor_sync(0xffffffffu, s1, o);
            }
            if (!lane) { spart[c][wid][0] = s0; spart[c][wid][1] = s1; }
        }
        red[t] = errp;
        __syncthreads();
        for (int s = 512; s; s >>= 1) { if (t < s) red[t] += red[t + s]; __syncthreads(); }
        // all pass work done; safe to overwrite cv (deterministic 32-way sum)
        if (t < NJ) {
            int c = t >> 1, k = t & 1;
            float s = 0.f;
            #pragma unroll
            for (int w = 0; w < 32; w++) s += spart[c][w][k];
            cv[t] = v / s;
        }
        if (!t) errS = red[0] / (float)(NC * HW);
        __syncthreads();
        if (errS < 0.01f) break;
    }
    if (t < NJ) g_cv[n * NJ + t] = cv[t];
}

// ---------------- 8. T output: full-chip elementwise r*c*K, block per (n,c) ----------------
__global__ void __launch_bounds__(256) k_tout(float* __restrict__ Tout) {
    int bc = blockIdx.x, n = bc / NC, c = bc % NC, t = threadIdx.x;
    const float2* Km2 = (const float2*)g_Kmat + (size_t)bc * HW;
    const float* rp = g_r + (size_t)bc * HW;
    float cv0 = g_cv[n * NJ + 2 * c], cv1 = g_cv[n * NJ + 2 * c + 1];
    float* T0 = Tout + (size_t)bc * 2 * HW;   // [n][c][k=0][m]
    float* T1 = T0 + HW;                      // [n][c][k=1][m]
    for (int m = t; m < HW; m += 256) {
        float2 kk = Km2[m];
        float r = rp[m];
        T0[m] = r * cv0 * kk.x;
        T1[m] = r * cv1 * kk.y;
    }
}

// ---------------- launcher ----------------
extern "C" void kernel_launch(void* const* d_in, const int* in_sizes, int n_in,
                              void* d_out, int out_size) {
    const float* norm_cam = (const float*)d_in[0];   // [8,21,64,64]
    const float* label    = (const float*)d_in[1];   // [8,21,1,1]
    const float* feature  = (const float*)d_in[2];   // [8,768,64,64]
    float* out  = (float*)d_out;                     // [8,21,64,64]
    float* Tout = out + NB * NC * HW;                // [8,21,2,64,64]

    const int KMEANS_SMEM = (2 * CF + KW * 2 * CF) * sizeof(float);      // 55296 B
    const int GEMM_SMEM   = GT * 256 * 4 + NJ * GT * 8;                  // 65280 B
    cudaFuncSetAttribute(k_kmeans, cudaFuncAttributeMaxDynamicSharedMemorySize, KMEANS_SMEM);
    cudaFuncSetAttribute(k_gemm,   cudaFuncAttributeMaxDynamicSharedMemorySize, GEMM_SMEM);

    k_transpose<<<dim3(HW / 32, CF / 32, NB), dim3(32, 8)>>>(feature);
    k_fnfin   <<<(NB * HW + 255) / 256, 256>>>();
    k_argmax  <<<(NB * HW + 255) / 256, 256>>>(norm_cam, label);
    k_lists   <<<NB, 672>>>();
    k_kmeans  <<<NB * NC, 32 * KW, KMEANS_SMEM>>>();
    k_gemm    <<<dim3(HW / 256, NB), 256, GEMM_SMEM>>>(feature);
    k_camkmat <<<NB * NC, 256>>>(label, out);
    k_sinkhorn<<<NB, 1024>>>();
    k_tout    <<<NB * NC, 256>>>(Tout);
}